// round 1
// baseline (speedup 1.0000x reference)
#include <cuda_runtime.h>
#include <cuda_bf16.h>

// Problem constants
#define BB 8
#define CC 128
#define HH 128
#define WW 128
#define HWSZ (HH*WW)          // 16384 = 2^14

// Scratch (device globals: allocation-free)
__device__ float g_off [(size_t)BB * 2 * CC * HWSZ];   // (B, 2C, H, W)  ~134MB
__device__ float g_xoff[(size_t)BB * CC * HWSZ];       // (B,  C, H, W)  ~67MB
__device__ float g_scale[CC];
__device__ float g_shift[CC];

// ---------------------------------------------------------------------------
// Tiled 3x3 conv, stride 1, pad 1, IC=128.
// Block tile: 128 output channels x 128 pixels (one full image row).
// grid.x = B*H  (row id), grid.y = OC/128. 256 threads, 8x8 outputs/thread.
// K-loop: 32 chunks of 4 input channels; smem holds 4ic x 3rows x 130cols of
// input and 36 x 128oc of weights per chunk.
// ---------------------------------------------------------------------------
__global__ __launch_bounds__(256, 2)
void conv3x3_kernel(const float* __restrict__ in,   // (B, 128, H, W)
                    const float* __restrict__ wgt,  // (OC, 128, 3, 3)
                    const float* __restrict__ bias, // (OC,) or nullptr
                    float* __restrict__ out,        // (B, OC, H, W)
                    int OC, int do_relu)
{
    const int row = blockIdx.x;           // 0 .. B*H-1
    const int b   = row >> 7;
    const int y   = row & 127;
    const int ocb = blockIdx.y << 7;      // oc block base

    __shared__ float s_in[4][3][132];     // [ic][ry][col], col 0 <-> x=-1
    __shared__ float s_w[36][132];        // [ic*9+t][oc]

    const int tid = threadIdx.x;
    const int tx  = tid & 15;             // pixel group
    const int ty  = tid >> 4;             // oc group

    float acc[8][8];
    #pragma unroll
    for (int i = 0; i < 8; i++)
        #pragma unroll
        for (int j = 0; j < 8; j++) acc[i][j] = 0.f;

    const float* inb = in + (size_t)b * CC * HWSZ;

    for (int kb = 0; kb < 32; kb++) {
        const int ic0 = kb << 2;

        // -- load input tile: 4 ic x 3 rows x 130 cols = 1560 elems
        for (int idx = tid; idx < 4 * 3 * 130; idx += 256) {
            int col = idx % 130;
            int rr  = idx / 130;
            int ic  = rr / 3;
            int ry  = rr - ic * 3;
            int gy  = y + ry - 1;
            int gx  = col - 1;
            float v = 0.f;
            if ((unsigned)gy < 128u && (unsigned)gx < 128u)
                v = inb[(size_t)(ic0 + ic) * HWSZ + gy * WW + gx];
            s_in[ic][ry][col] = v;
        }
        // -- load weight tile: 128 oc x 36 (= 4ic x 9 taps), contiguous per oc
        #pragma unroll
        for (int l = 0; l < 18; l++) {
            int idx = tid + l * 256;             // 4608 total
            int oc  = idx / 36;
            int u   = idx - oc * 36;
            s_w[u][oc] = wgt[(size_t)(ocb + oc) * (CC * 9) + ic0 * 9 + u];
        }
        __syncthreads();

        // -- compute 36 k-steps
        #pragma unroll
        for (int ic = 0; ic < 4; ic++) {
            #pragma unroll
            for (int t = 0; t < 9; t++) {
                const int ky = t / 3;
                const int kx = t - ky * 3;
                float a[8], bv[8];
                #pragma unroll
                for (int i = 0; i < 8; i++) a[i] = s_w[ic * 9 + t][ty * 8 + i];
                #pragma unroll
                for (int j = 0; j < 8; j++) bv[j] = s_in[ic][ky][tx + 16 * j + kx];
                #pragma unroll
                for (int i = 0; i < 8; i++)
                    #pragma unroll
                    for (int j = 0; j < 8; j++)
                        acc[i][j] = fmaf(a[i], bv[j], acc[i][j]);
            }
        }
        __syncthreads();
    }

    // -- epilogue: bias, relu, store
    #pragma unroll
    for (int i = 0; i < 8; i++) {
        const int oc = ocb + ty * 8 + i;
        const float bvl = bias ? bias[oc] : 0.f;
        float* op = out + ((size_t)b * OC + oc) * HWSZ + y * WW;
        #pragma unroll
        for (int j = 0; j < 8; j++) {
            float v = acc[i][j] + bvl;
            if (do_relu) v = fmaxf(v, 0.f);
            op[tx + 16 * j] = v;
        }
    }
}

// ---------------------------------------------------------------------------
// Deformable bilinear sampling, faithful to the reference's quirky reshape:
// for sample channel c, the (y,x) offset pair of flat pixel q lives at
// offsets_flat[b*2C*HW + c*2*HW + 2q + {0,1}].
// ---------------------------------------------------------------------------
__global__ void deform_kernel(const float* __restrict__ x,
                              const float* __restrict__ off,
                              float* __restrict__ xo)
{
    const int gid = blockIdx.x * 256 + threadIdx.x;     // < B*C*HW = 16.8M
    const int q = gid & (HWSZ - 1);
    const int p = gid >> 14;                            // b*C + c
    const int i = q >> 7;                               // row
    const int j = q & 127;                              // col

    const float* ob = off + (size_t)p * 2 * HWSZ + 2 * q;
    const float oy = ob[0];
    const float ox = ob[1];

    float yc = fminf(fmaxf(oy + (float)i, 0.f), 127.f);
    float xc = fminf(fmaxf(ox + (float)j, 0.f), 127.f);
    float y0f = floorf(yc), y1f = ceilf(yc);
    float x0f = floorf(xc), x1f = ceilf(xc);
    int y0 = (int)y0f, y1 = (int)y1f;
    int x0 = (int)x0f, x1 = (int)x1f;

    const float* img = x + (size_t)p * HWSZ;
    float v_lt = img[y0 * WW + x0];
    float v_rb = img[y1 * WW + x1];
    float v_lb = img[y0 * WW + x1];
    float v_rt = img[y1 * WW + x0];

    float dy = yc - y0f;
    float dx = xc - x0f;
    float v_t = v_lt + (v_rt - v_lt) * dy;
    float v_b = v_lb + (v_rb - v_lb) * dy;
    xo[gid] = v_t + (v_b - v_t) * dx;
}

// ---------------------------------------------------------------------------
// BatchNorm statistics: one block per channel. Computes per-channel
// scale = gamma * rsqrt(var + eps), shift = beta - mean*scale.
// ---------------------------------------------------------------------------
__global__ void bn_stats_kernel(const float* __restrict__ ych,
                                const float* __restrict__ gamma,
                                const float* __restrict__ beta)
{
    const int c = blockIdx.x;
    float s = 0.f, s2 = 0.f;
    for (int b = 0; b < BB; b++) {
        const float* p = ych + ((size_t)b * CC + c) * HWSZ;
        for (int q = threadIdx.x; q < HWSZ; q += 256) {
            float v = p[q];
            s += v;
            s2 += v * v;
        }
    }
    __shared__ float rs[256], rs2[256];
    rs[threadIdx.x] = s;
    rs2[threadIdx.x] = s2;
    __syncthreads();
    for (int st = 128; st > 0; st >>= 1) {
        if (threadIdx.x < st) {
            rs[threadIdx.x]  += rs[threadIdx.x + st];
            rs2[threadIdx.x] += rs2[threadIdx.x + st];
        }
        __syncthreads();
    }
    if (threadIdx.x == 0) {
        const float n = (float)(BB * HWSZ);
        float mean = rs[0] / n;
        float var  = rs2[0] / n - mean * mean;
        float sc   = gamma[c] * rsqrtf(var + 1e-5f);
        g_scale[c] = sc;
        g_shift[c] = beta[c] - mean * sc;
    }
}

__global__ void bn_apply_kernel(float* __restrict__ ych)
{
    const int gid = blockIdx.x * 256 + threadIdx.x;
    const int c = (gid >> 14) & 127;
    ych[gid] = fmaf(ych[gid], g_scale[c], g_shift[c]);
}

// ---------------------------------------------------------------------------
extern "C" void kernel_launch(void* const* d_in, const int* in_sizes, int n_in,
                              void* d_out, int out_size)
{
    const float* x      = (const float*)d_in[0];
    const float* w_off  = (const float*)d_in[1];
    const float* w_conv = (const float*)d_in[2];
    const float* b_conv = (const float*)d_in[3];
    const float* gamma  = (const float*)d_in[4];
    const float* beta   = (const float*)d_in[5];
    float* out = (float*)d_out;

    float* off;  cudaGetSymbolAddress((void**)&off,  g_off);
    float* xoff; cudaGetSymbolAddress((void**)&xoff, g_xoff);

    // 1) offsets = conv3x3(x, w_off)  (no bias, no relu), OC=256
    dim3 g1(BB * HH, 2);
    conv3x3_kernel<<<g1, 256>>>(x, w_off, nullptr, off, 256, 0);

    // 2) deformable bilinear sampling
    const int nelem = BB * CC * HWSZ;
    deform_kernel<<<nelem / 256, 256>>>(x, off, xoff);

    // 3) y = relu(conv3x3(x_off, w_conv) + b_conv), OC=128  -> d_out
    dim3 g2(BB * HH, 1);
    conv3x3_kernel<<<g2, 256>>>(xoff, w_conv, b_conv, out, 128, 1);

    // 4) batchnorm (training stats) in-place on d_out
    bn_stats_kernel<<<CC, 256>>>(out, gamma, beta);
    bn_apply_kernel<<<nelem / 256, 256>>>(out);
}

// round 2
// speedup vs baseline: 1.0877x; 1.0877x over previous
#include <cuda_runtime.h>
#include <cuda_bf16.h>

// Problem constants
#define BB 8
#define CC 128
#define HH 128
#define WW 128
#define HWSZ (HH*WW)          // 16384 = 2^14

// Scratch (device globals: allocation-free)
__device__ float g_off [(size_t)BB * 2 * CC * HWSZ];   // (B, 2C, H, W)  ~134MB
__device__ float g_xoff[(size_t)BB * CC * HWSZ];       // (B,  C, H, W)  ~67MB
__device__ float g_part[CC][BB][2];                    // per (c,b) partial sums
__device__ float g_scale[CC];
__device__ float g_shift[CC];

// Packed fp32x2 FMA (Blackwell sm_103a): d = a*b + c on both lanes of the pair.
#define FMA_F32X2(d, a, b, c) \
    asm("fma.rn.f32x2 %0, %1, %2, %3;" : "=l"(d) : "l"(a), "l"(b), "l"(c))
#define PACK_BCAST_F32X2(d, v) \
    asm("mov.b64 %0, {%1, %1};" : "=l"(d) : "r"(__float_as_uint(v)))

// ---------------------------------------------------------------------------
// Tiled 3x3 conv, stride 1, pad 1, IC=128, packed-f32x2 inner loop.
// Block tile: 128 output channels x 128 pixels (one full image row).
// grid.x = B*H (row id), grid.y = OC/128. 256 threads, 8x8 outputs/thread
// (held as 4 f32x2 pairs x 8).
// ---------------------------------------------------------------------------
__global__ __launch_bounds__(256, 2)
void conv3x3_kernel(const float* __restrict__ in,   // (B, 128, H, W)
                    const float* __restrict__ wgt,  // (OC, 128, 3, 3)
                    const float* __restrict__ bias, // (OC,) or nullptr
                    float* __restrict__ out,        // (B, OC, H, W)
                    int OC, int do_relu)
{
    const int row = blockIdx.x;           // 0 .. B*H-1
    const int b   = row >> 7;
    const int y   = row & 127;
    const int ocb = blockIdx.y << 7;      // oc block base

    __shared__ float s_in[4][3][132];     // [ic][ry][col], col 0 <-> x=-1
    __shared__ float s_w[36][132];        // [ic*9+t][oc]  (row = 528B, 16B-aligned)

    const int tid = threadIdx.x;
    const int tx  = tid & 15;             // pixel group
    const int ty  = tid >> 4;             // oc group

    // 4 oc-pairs x 8 pixels, packed f32x2
    unsigned long long acc[4][8];
    #pragma unroll
    for (int i = 0; i < 4; i++)
        #pragma unroll
        for (int j = 0; j < 8; j++) acc[i][j] = 0ull;

    const float* inb = in + (size_t)b * CC * HWSZ;

    for (int kb = 0; kb < 32; kb++) {
        const int ic0 = kb << 2;

        // -- load input tile: 4 ic x 3 rows x 130 cols
        for (int idx = tid; idx < 4 * 3 * 130; idx += 256) {
            int col = idx % 130;
            int rr  = idx / 130;
            int ic  = rr / 3;
            int ry  = rr - ic * 3;
            int gy  = y + ry - 1;
            int gx  = col - 1;
            float v = 0.f;
            if ((unsigned)gy < 128u && (unsigned)gx < 128u)
                v = inb[(size_t)(ic0 + ic) * HWSZ + gy * WW + gx];
            s_in[ic][ry][col] = v;
        }
        // -- load weight tile: 128 oc x 36 (= 4ic x 9 taps)
        #pragma unroll
        for (int l = 0; l < 18; l++) {
            int idx = tid + l * 256;             // 4608 total
            int oc  = idx / 36;
            int u   = idx - oc * 36;
            s_w[u][oc] = wgt[(size_t)(ocb + oc) * (CC * 9) + ic0 * 9 + u];
        }
        __syncthreads();

        // -- compute 36 k-steps, FFMA2 inner loop
        #pragma unroll
        for (int ic = 0; ic < 4; ic++) {
            #pragma unroll
            for (int t = 0; t < 9; t++) {
                const int ky = t / 3;
                const int kx = t - ky * 3;
                // a-pairs: weights for 8 consecutive oc -> 4 f32x2 pairs,
                // loaded as 2x LDS.128 with zero repack cost.
                const ulonglong2* wp =
                    (const ulonglong2*)&s_w[ic * 9 + t][ty * 8];
                ulonglong2 p01 = wp[0];
                ulonglong2 p23 = wp[1];
                unsigned long long apair[4] = {p01.x, p01.y, p23.x, p23.y};
                #pragma unroll
                for (int j = 0; j < 8; j++) {
                    float bj = s_in[ic][ky][tx + 16 * j + kx];
                    unsigned long long bp;
                    PACK_BCAST_F32X2(bp, bj);
                    #pragma unroll
                    for (int i = 0; i < 4; i++)
                        FMA_F32X2(acc[i][j], apair[i], bp, acc[i][j]);
                }
            }
        }
        __syncthreads();
    }

    // -- epilogue: bias, relu, store
    #pragma unroll
    for (int i = 0; i < 4; i++) {
        const int oc0 = ocb + ty * 8 + 2 * i;
        const float b0 = bias ? bias[oc0]     : 0.f;
        const float b1 = bias ? bias[oc0 + 1] : 0.f;
        float* op0 = out + ((size_t)b * OC + oc0)     * HWSZ + y * WW;
        float* op1 = out + ((size_t)b * OC + oc0 + 1) * HWSZ + y * WW;
        #pragma unroll
        for (int j = 0; j < 8; j++) {
            unsigned int lo, hi;
            asm("mov.b64 {%0, %1}, %2;" : "=r"(lo), "=r"(hi) : "l"(acc[i][j]));
            float v0 = __uint_as_float(lo) + b0;
            float v1 = __uint_as_float(hi) + b1;
            if (do_relu) { v0 = fmaxf(v0, 0.f); v1 = fmaxf(v1, 0.f); }
            op0[tx + 16 * j] = v0;
            op1[tx + 16 * j] = v1;
        }
    }
}

// ---------------------------------------------------------------------------
// Deformable bilinear sampling, faithful to the reference's quirky reshape:
// for sample channel c, the (y,x) offset pair of flat pixel q lives at
// offsets_flat[b*2C*HW + c*2*HW + 2q + {0,1}].
// ---------------------------------------------------------------------------
__global__ void deform_kernel(const float* __restrict__ x,
                              const float* __restrict__ off,
                              float* __restrict__ xo)
{
    const int gid = blockIdx.x * 256 + threadIdx.x;     // < B*C*HW = 16.8M
    const int q = gid & (HWSZ - 1);
    const int p = gid >> 14;                            // b*C + c
    const int i = q >> 7;                               // row
    const int j = q & 127;                              // col

    const float2 o2 = *(const float2*)(off + (size_t)p * 2 * HWSZ + 2 * q);
    const float oy = o2.x;
    const float ox = o2.y;

    float yc = fminf(fmaxf(oy + (float)i, 0.f), 127.f);
    float xc = fminf(fmaxf(ox + (float)j, 0.f), 127.f);
    float y0f = floorf(yc), y1f = ceilf(yc);
    float x0f = floorf(xc), x1f = ceilf(xc);
    int y0 = (int)y0f, y1 = (int)y1f;
    int x0 = (int)x0f, x1 = (int)x1f;

    const float* img = x + (size_t)p * HWSZ;
    float v_lt = img[y0 * WW + x0];
    float v_rb = img[y1 * WW + x1];
    float v_lb = img[y0 * WW + x1];
    float v_rt = img[y1 * WW + x0];

    float dy = yc - y0f;
    float dx = xc - x0f;
    float v_t = v_lt + (v_rt - v_lt) * dy;
    float v_b = v_lb + (v_rb - v_lb) * dy;
    xo[gid] = v_t + (v_b - v_t) * dx;
}

// ---------------------------------------------------------------------------
// BatchNorm statistics, deterministic 2-stage: per-(c,b) partials, then
// finalize. grid = (C, B) fills the chip (1024 blocks).
// ---------------------------------------------------------------------------
__global__ void bn_stats_kernel(const float* __restrict__ ych)
{
    const int c = blockIdx.x;
    const int b = blockIdx.y;
    const float* p = ych + ((size_t)b * CC + c) * HWSZ;
    float s = 0.f, s2 = 0.f;
    for (int q = threadIdx.x; q < HWSZ; q += 256) {
        float v = p[q];
        s += v;
        s2 += v * v;
    }
    __shared__ float rs[256], rs2[256];
    rs[threadIdx.x] = s;
    rs2[threadIdx.x] = s2;
    __syncthreads();
    for (int st = 128; st > 0; st >>= 1) {
        if (threadIdx.x < st) {
            rs[threadIdx.x]  += rs[threadIdx.x + st];
            rs2[threadIdx.x] += rs2[threadIdx.x + st];
        }
        __syncthreads();
    }
    if (threadIdx.x == 0) {
        g_part[c][b][0] = rs[0];
        g_part[c][b][1] = rs2[0];
    }
}

__global__ void bn_finalize_kernel(const float* __restrict__ gamma,
                                   const float* __restrict__ beta)
{
    const int c = threadIdx.x;   // 128 threads
    float s = 0.f, s2 = 0.f;
    #pragma unroll
    for (int b = 0; b < BB; b++) {
        s  += g_part[c][b][0];
        s2 += g_part[c][b][1];
    }
    const float n = (float)(BB * HWSZ);
    float mean = s / n;
    float var  = s2 / n - mean * mean;
    float sc   = gamma[c] * rsqrtf(var + 1e-5f);
    g_scale[c] = sc;
    g_shift[c] = beta[c] - mean * sc;
}

__global__ void bn_apply_kernel(float* __restrict__ ych)
{
    const int gid = blockIdx.x * 256 + threadIdx.x;
    const int c = (gid >> 14) & 127;
    ych[gid] = fmaf(ych[gid], g_scale[c], g_shift[c]);
}

// ---------------------------------------------------------------------------
extern "C" void kernel_launch(void* const* d_in, const int* in_sizes, int n_in,
                              void* d_out, int out_size)
{
    const float* x      = (const float*)d_in[0];
    const float* w_off  = (const float*)d_in[1];
    const float* w_conv = (const float*)d_in[2];
    const float* b_conv = (const float*)d_in[3];
    const float* gamma  = (const float*)d_in[4];
    const float* beta   = (const float*)d_in[5];
    float* out = (float*)d_out;

    float* off;  cudaGetSymbolAddress((void**)&off,  g_off);
    float* xoff; cudaGetSymbolAddress((void**)&xoff, g_xoff);

    // 1) offsets = conv3x3(x, w_off)  (no bias, no relu), OC=256
    dim3 g1(BB * HH, 2);
    conv3x3_kernel<<<g1, 256>>>(x, w_off, nullptr, off, 256, 0);

    // 2) deformable bilinear sampling
    const int nelem = BB * CC * HWSZ;
    deform_kernel<<<nelem / 256, 256>>>(x, off, xoff);

    // 3) y = relu(conv3x3(x_off, w_conv) + b_conv), OC=128  -> d_out
    dim3 g2(BB * HH, 1);
    conv3x3_kernel<<<g2, 256>>>(xoff, w_conv, b_conv, out, 128, 1);

    // 4) batchnorm (training stats) in-place on d_out
    dim3 gs(CC, BB);
    bn_stats_kernel<<<gs, 256>>>(out);
    bn_finalize_kernel<<<1, CC>>>(gamma, beta);
    bn_apply_kernel<<<nelem / 256, 256>>>(out);
}

// round 4
// speedup vs baseline: 1.3178x; 1.2115x over previous
#include <cuda_runtime.h>
#include <cuda_bf16.h>
#include <cstdint>

// Problem constants
#define BB 8
#define CC 128
#define HH 128
#define WW 128
#define HWSZ (HH*WW)          // 16384

// Scratch (device globals: allocation-free)
__device__ float g_off  [(size_t)BB * 2 * CC * HWSZ];   // conv1 out (B,2C,H,W)
__device__ float g_xoff [(size_t)BB * CC * HWSZ];       // deform out (B,C,H,W)
__device__ float g_xT   [(size_t)BB * HWSZ * CC];       // x    transposed (B,H,W,C), tf32
__device__ float g_xoffT[(size_t)BB * HWSZ * CC];       // xoff transposed (B,H,W,C), tf32
__device__ float g_wp1  [(size_t)9 * 256 * 128];        // w_off  packed (t,oc,ic), tf32
__device__ float g_wp2  [(size_t)9 * 128 * 128];        // w_conv packed (t,oc,ic), tf32
__device__ float g_part[CC][BB][2];
__device__ float g_scale[CC];
__device__ float g_shift[CC];

__device__ __forceinline__ float tf32r(float v) {
    float r;
    asm("cvt.rna.tf32.f32 %0, %1;" : "=f"(r) : "f"(v));
    return r;
}

// ---------------------------------------------------------------------------
// Implicit-GEMM conv 3x3 via warp-level tf32 mma.sync (sm_80+ path; the
// harness's ptxas target is plain sm_103, so tcgen05 is unavailable).
// CTA: D[128 oc x 128 px] for one image row (b, y), oc block ocb.
// K = 1152 = 8 chunks x (9 taps x 16 ic); im2col materialized at fill time.
// 8 warps as 2 (m) x 4 (n); warp tile 64 oc x 32 px; m16n8k8 fragments.
// SMEM tiles row-major [row][k], row stride 148 floats (148%32==20 ->
// conflict-free fragment LDS: banks r*20+c cover all 32).
// ---------------------------------------------------------------------------
#define KCH   144
#define LDA   148
#define TILE_BYTES (128 * LDA * 4)            // 75776
#define SMEM_TOTAL_CONV (2 * TILE_BYTES)      // 151552
#define LDT   132                             // epilogue transpose stride

__global__ void __launch_bounds__(256, 1)
conv_mma_kernel(const float* __restrict__ xT,   // (B,H,W,C) tf32
                const float* __restrict__ wp,   // (9,OC,128) tf32
                const float* __restrict__ bias, // (OC,) or nullptr
                float* __restrict__ out,        // (B,OC,H,W)
                int OC, int do_relu)
{
    extern __shared__ char smem[];
    float* sA = (float*)smem;                 // weights  [oc][k]
    float* sB = (float*)(smem + TILE_BYTES);  // im2col   [px][k]

    const int tid  = threadIdx.x;
    const int wid  = tid >> 5;
    const int lane = tid & 31;
    const int wm   = wid & 1;                 // warp m (2)
    const int wn   = wid >> 1;                // warp n (4)
    const int lr   = lane >> 2;               // fragment row 0..7
    const int lc   = lane & 3;                // fragment col 0..3

    const int row = blockIdx.x;
    const int b   = row >> 7;
    const int y   = row & 127;
    const int ocb = blockIdx.y << 7;

    float acc[4][4][4];
    #pragma unroll
    for (int mt = 0; mt < 4; mt++)
        #pragma unroll
        for (int nt = 0; nt < 4; nt++)
            #pragma unroll
            for (int i = 0; i < 4; i++) acc[mt][nt][i] = 0.f;

    for (int kb = 0; kb < 8; kb++) {
        const int ic0 = kb << 4;
        __syncthreads();   // previous compute done before overwrite

        // ---- fill A (weights) and B (im2col input): 4608 float4 each
        for (int v = tid; v < 2 * 4608; v += 256) {
            const int which = (v >= 4608);
            const int u  = which ? v - 4608 : v;
            const int r  = u / 36;            // oc (A) or pixel (B)
            const int k4 = u - r * 36;
            const int t  = k4 >> 2;           // tap 0..8
            const int g  = k4 & 3;            // ic float4 group
            float4 val;
            if (!which) {
                val = *(const float4*)(wp + ((size_t)(t * OC + ocb + r)) * 128 + ic0 + g * 4);
            } else {
                const int gy = y + t / 3 - 1;
                const int gx = r + t % 3 - 1;
                if ((unsigned)gy < 128u && (unsigned)gx < 128u)
                    val = *(const float4*)(xT + (((size_t)b * 128 + gy) * 128 + gx) * 128 + ic0 + g * 4);
                else
                    val = make_float4(0.f, 0.f, 0.f, 0.f);
            }
            float* dst = (which ? sB : sA) + r * LDA + t * 16 + g * 4;
            *(float4*)dst = val;
        }
        __syncthreads();

        // ---- 18 k8-steps of 16 MMAs
        #pragma unroll 2
        for (int s = 0; s < 18; s++) {
            const int k0 = s << 3;
            uint32_t af[4][4], bf[4][2];
            #pragma unroll
            for (int mt = 0; mt < 4; mt++) {
                const float* ap = sA + (wm * 64 + mt * 16 + lr) * LDA + k0 + lc;
                af[mt][0] = __float_as_uint(ap[0]);
                af[mt][1] = __float_as_uint(ap[8 * LDA]);
                af[mt][2] = __float_as_uint(ap[4]);
                af[mt][3] = __float_as_uint(ap[8 * LDA + 4]);
            }
            #pragma unroll
            for (int nt = 0; nt < 4; nt++) {
                const float* bp = sB + (wn * 32 + nt * 8 + lr) * LDA + k0 + lc;
                bf[nt][0] = __float_as_uint(bp[0]);
                bf[nt][1] = __float_as_uint(bp[4]);
            }
            #pragma unroll
            for (int mt = 0; mt < 4; mt++)
                #pragma unroll
                for (int nt = 0; nt < 4; nt++)
                    asm volatile(
                        "mma.sync.aligned.m16n8k8.row.col.f32.tf32.tf32.f32 "
                        "{%0,%1,%2,%3}, {%4,%5,%6,%7}, {%8,%9}, {%0,%1,%2,%3};"
                        : "+f"(acc[mt][nt][0]), "+f"(acc[mt][nt][1]),
                          "+f"(acc[mt][nt][2]), "+f"(acc[mt][nt][3])
                        : "r"(af[mt][0]), "r"(af[mt][1]), "r"(af[mt][2]), "r"(af[mt][3]),
                          "r"(bf[nt][0]), "r"(bf[nt][1]));
        }
    }

    // ---- epilogue: bias + relu into SMEM transpose buffer, coalesced store
    __syncthreads();
    float* s_t = (float*)smem;                // reuse, [oc][px] stride LDT
    #pragma unroll
    for (int mt = 0; mt < 4; mt++) {
        const int r0 = wm * 64 + mt * 16 + lr;
        const float bv0 = bias ? bias[ocb + r0]     : 0.f;
        const float bv1 = bias ? bias[ocb + r0 + 8] : 0.f;
        #pragma unroll
        for (int nt = 0; nt < 4; nt++) {
            const int c0 = wn * 32 + nt * 8 + 2 * lc;
            float v0 = acc[mt][nt][0] + bv0;
            float v1 = acc[mt][nt][1] + bv0;
            float v2 = acc[mt][nt][2] + bv1;
            float v3 = acc[mt][nt][3] + bv1;
            if (do_relu) {
                v0 = fmaxf(v0, 0.f); v1 = fmaxf(v1, 0.f);
                v2 = fmaxf(v2, 0.f); v3 = fmaxf(v3, 0.f);
            }
            *(float2*)(s_t + r0 * LDT + c0)       = make_float2(v0, v1);
            *(float2*)(s_t + (r0 + 8) * LDT + c0) = make_float2(v2, v3);
        }
    }
    __syncthreads();

    for (int idx = tid; idx < 128 * 32; idx += 256) {
        const int oc = idx >> 5;
        const int xg = idx & 31;
        float4 v = *(float4*)(s_t + oc * LDT + xg * 4);
        *(float4*)(out + ((size_t)b * OC + ocb + oc) * HWSZ + y * WW + xg * 4) = v;
    }
}

// ---------------------------------------------------------------------------
// Transpose (B,C,HW) -> (B,HW,C) with tf32 rounding.
// ---------------------------------------------------------------------------
__global__ void transpose_tf32_kernel(const float* __restrict__ in,
                                      float* __restrict__ outT)
{
    __shared__ float tile[32][33];
    const int b  = blockIdx.z;
    const int c0 = blockIdx.y << 5;
    const int q0 = blockIdx.x << 5;
    const int tx = threadIdx.x;          // 32
    const int ty = threadIdx.y;          // 8
    #pragma unroll
    for (int i = ty; i < 32; i += 8)
        tile[i][tx] = in[((size_t)b * CC + c0 + i) * HWSZ + q0 + tx];
    __syncthreads();
    #pragma unroll
    for (int j = ty; j < 32; j += 8)
        outT[((size_t)b * HWSZ + q0 + j) * CC + c0 + tx] = tf32r(tile[tx][j]);
}

// Pack weights (OC,128,3,3) -> (9,OC,128), tf32-rounded.
__global__ void pack_w_kernel(const float* __restrict__ w,
                              float* __restrict__ wpk, int OC)
{
    const int idx = blockIdx.x * 256 + threadIdx.x;
    if (idx >= OC * 128 * 9) return;
    const int oc = idx / (128 * 9);
    const int r  = idx - oc * (128 * 9);
    const int ic = r / 9;
    const int t  = r - ic * 9;
    wpk[((size_t)t * OC + oc) * 128 + ic] = tf32r(w[idx]);
}

// ---------------------------------------------------------------------------
// Deformable bilinear sampling (quirky reshape semantics, full fp32).
// ---------------------------------------------------------------------------
__global__ void deform_kernel(const float* __restrict__ x,
                              const float* __restrict__ off,
                              float* __restrict__ xo)
{
    const int gid = blockIdx.x * 256 + threadIdx.x;
    const int q = gid & (HWSZ - 1);
    const int p = gid >> 14;
    const int i = q >> 7;
    const int j = q & 127;

    const float2 o2 = *(const float2*)(off + (size_t)p * 2 * HWSZ + 2 * q);
    float yc = fminf(fmaxf(o2.x + (float)i, 0.f), 127.f);
    float xc = fminf(fmaxf(o2.y + (float)j, 0.f), 127.f);
    float y0f = floorf(yc), y1f = ceilf(yc);
    float x0f = floorf(xc), x1f = ceilf(xc);
    int y0 = (int)y0f, y1 = (int)y1f;
    int x0 = (int)x0f, x1 = (int)x1f;

    const float* img = x + (size_t)p * HWSZ;
    float v_lt = img[y0 * WW + x0];
    float v_rb = img[y1 * WW + x1];
    float v_lb = img[y0 * WW + x1];
    float v_rt = img[y1 * WW + x0];

    float dy = yc - y0f;
    float dx = xc - x0f;
    float v_t = v_lt + (v_rt - v_lt) * dy;
    float v_b = v_lb + (v_rb - v_lb) * dy;
    xo[gid] = v_t + (v_b - v_t) * dx;
}

// ---------------------------------------------------------------------------
// BatchNorm (training stats), deterministic 2-stage.
// ---------------------------------------------------------------------------
__global__ void bn_stats_kernel(const float* __restrict__ ych)
{
    const int c = blockIdx.x;
    const int b = blockIdx.y;
    const float* p = ych + ((size_t)b * CC + c) * HWSZ;
    float s = 0.f, s2 = 0.f;
    for (int q = threadIdx.x; q < HWSZ; q += 256) {
        float v = p[q];
        s += v; s2 += v * v;
    }
    __shared__ float rs[256], rs2[256];
    rs[threadIdx.x] = s; rs2[threadIdx.x] = s2;
    __syncthreads();
    for (int st = 128; st > 0; st >>= 1) {
        if (threadIdx.x < st) {
            rs[threadIdx.x]  += rs[threadIdx.x + st];
            rs2[threadIdx.x] += rs2[threadIdx.x + st];
        }
        __syncthreads();
    }
    if (threadIdx.x == 0) { g_part[c][b][0] = rs[0]; g_part[c][b][1] = rs2[0]; }
}

__global__ void bn_finalize_kernel(const float* __restrict__ gamma,
                                   const float* __restrict__ beta)
{
    const int c = threadIdx.x;
    float s = 0.f, s2 = 0.f;
    #pragma unroll
    for (int b = 0; b < BB; b++) { s += g_part[c][b][0]; s2 += g_part[c][b][1]; }
    const float n = (float)(BB * HWSZ);
    float mean = s / n;
    float var  = s2 / n - mean * mean;
    float sc   = gamma[c] * rsqrtf(var + 1e-5f);
    g_scale[c] = sc;
    g_shift[c] = beta[c] - mean * sc;
}

__global__ void bn_apply_kernel(float* __restrict__ ych)
{
    const int gid = blockIdx.x * 256 + threadIdx.x;
    const int c = (gid >> 14) & 127;
    ych[gid] = fmaf(ych[gid], g_scale[c], g_shift[c]);
}

// ---------------------------------------------------------------------------
extern "C" void kernel_launch(void* const* d_in, const int* in_sizes, int n_in,
                              void* d_out, int out_size)
{
    const float* x      = (const float*)d_in[0];
    const float* w_off  = (const float*)d_in[1];
    const float* w_conv = (const float*)d_in[2];
    const float* b_conv = (const float*)d_in[3];
    const float* gamma  = (const float*)d_in[4];
    const float* beta   = (const float*)d_in[5];
    float* out = (float*)d_out;

    float *off, *xoff, *xT, *xoffT, *wp1, *wp2;
    cudaGetSymbolAddress((void**)&off,   g_off);
    cudaGetSymbolAddress((void**)&xoff,  g_xoff);
    cudaGetSymbolAddress((void**)&xT,    g_xT);
    cudaGetSymbolAddress((void**)&xoffT, g_xoffT);
    cudaGetSymbolAddress((void**)&wp1,   g_wp1);
    cudaGetSymbolAddress((void**)&wp2,   g_wp2);

    cudaFuncSetAttribute(conv_mma_kernel,
                         cudaFuncAttributeMaxDynamicSharedMemorySize, SMEM_TOTAL_CONV);

    // 0) transpose x -> xT (tf32), pack both weight tensors
    dim3 tg(HWSZ / 32, CC / 32, BB), tb(32, 8);
    transpose_tf32_kernel<<<tg, tb>>>(x, xT);
    pack_w_kernel<<<(256 * 128 * 9 + 255) / 256, 256>>>(w_off, wp1, 256);
    pack_w_kernel<<<(128 * 128 * 9 + 255) / 256, 256>>>(w_conv, wp2, 128);

    // 1) offsets = conv3x3(x, w_off), OC=256
    dim3 g1(BB * HH, 2);
    conv_mma_kernel<<<g1, 256, SMEM_TOTAL_CONV>>>(xT, wp1, nullptr, off, 256, 0);

    // 2) deformable bilinear sampling (fp32), then transpose -> xoffT (tf32)
    const int nelem = BB * CC * HWSZ;
    deform_kernel<<<nelem / 256, 256>>>(x, off, xoff);
    transpose_tf32_kernel<<<tg, tb>>>(xoff, xoffT);

    // 3) y = relu(conv3x3(x_off, w_conv) + b_conv), OC=128 -> d_out
    dim3 g2(BB * HH, 1);
    conv_mma_kernel<<<g2, 256, SMEM_TOTAL_CONV>>>(xoffT, wp2, b_conv, out, 128, 1);

    // 4) batchnorm (training stats) in-place on d_out
    dim3 gs(CC, BB);
    bn_stats_kernel<<<gs, 256>>>(out);
    bn_finalize_kernel<<<1, CC>>>(gamma, beta);
    bn_apply_kernel<<<nelem / 256, 256>>>(out);
}

// round 5
// speedup vs baseline: 2.6038x; 1.9758x over previous
#include <cuda_runtime.h>
#include <cuda_bf16.h>
#include <cstdint>

// Problem constants
#define BB 8
#define CC 128
#define HH 128
#define WW 128
#define HWSZ (HH*WW)          // 16384

// Scratch (device globals: allocation-free)
__device__ float g_off  [(size_t)BB * 2 * CC * HWSZ];   // conv1 out (B,2C,H,W)
__device__ float g_xT   [(size_t)BB * HWSZ * CC];       // x    transposed (B,H,W,C), tf32
__device__ float g_xoffT[(size_t)BB * HWSZ * CC];       // deformed, transposed (B,H,W,C), tf32
__device__ float g_wp1  [(size_t)9 * 256 * 128];        // w_off  packed (t,oc,ic), tf32
__device__ float g_wp2  [(size_t)9 * 128 * 128];        // w_conv packed (t,oc,ic), tf32
__device__ float g_part[CC][BB][2];
__device__ float g_scale[CC];
__device__ float g_shift[CC];

__device__ __forceinline__ float tf32r(float v) {
    float r;
    asm("cvt.rna.tf32.f32 %0, %1;" : "=f"(r) : "f"(v));
    return r;
}
__device__ __forceinline__ uint32_t smem_u32(const void* p) {
    uint32_t a;
    asm("{ .reg .u64 t; cvta.to.shared.u64 t, %1; cvt.u32.u64 %0, t; }"
        : "=r"(a) : "l"(p));
    return a;
}
#define CP_ASYNC16(dst, src, sz) \
    asm volatile("cp.async.cg.shared.global [%0], [%1], 16, %2;" \
                 :: "r"(dst), "l"(src), "r"(sz))
#define CP_COMMIT()  asm volatile("cp.async.commit_group;")
#define CP_WAIT1()   asm volatile("cp.async.wait_group 1;")
#define CP_WAIT0()   asm volatile("cp.async.wait_group 0;")
#define LDSM_X4(r0, r1, r2, r3, addr) \
    asm volatile("ldmatrix.sync.aligned.m8n8.x4.shared.b16 {%0,%1,%2,%3}, [%4];" \
                 : "=r"(r0), "=r"(r1), "=r"(r2), "=r"(r3) : "r"(addr))

// ---------------------------------------------------------------------------
// Implicit-GEMM conv 3x3 via warp-level tf32 mma.sync, cp.async 2-stage
// pipeline, ldmatrix fragment loads.
// CTA: D[128 oc x 128 px] for one image row (b, y), oc block ocb.
// K = 1152 = 16 chunks x (9 taps x 8 ic); im2col materialized at fill time.
// 8 warps as 2 (m) x 4 (n); warp tile 64 oc x 32 px; m16n8k8 fragments.
// SMEM tiles row-major [row][k], row stride LDA=76 floats (conflict-free:
// row-start banks r*12 mod 32 cover 8 disjoint 4-bank spans).
// ---------------------------------------------------------------------------
#define KCH    72                           // K per chunk (9 taps x 8 ic)
#define LDA    76
#define ATILE  (128 * LDA * 4)              // 38912 B
#define STAGE  (2 * ATILE)                  // 77824 B  (A then B)
#define SMEM_TOTAL_CONV (2 * STAGE)         // 155648 B
#define LDT    132                          // epilogue transpose stride

__global__ void __launch_bounds__(256, 1)
conv_mma_kernel(const float* __restrict__ xT,   // (B,H,W,C) tf32
                const float* __restrict__ wp,   // (9,OC,128) tf32
                const float* __restrict__ bias, // (OC,) or nullptr
                float* __restrict__ out,        // (B,OC,H,W)
                int OC, int do_relu)
{
    extern __shared__ char smem[];
    const uint32_t sbase = smem_u32(smem);

    const int tid  = threadIdx.x;
    const int wid  = tid >> 5;
    const int lane = tid & 31;
    const int wm   = wid & 1;                 // warp m (2)
    const int wn   = wid >> 1;                // warp n (4)

    const int row = blockIdx.x;
    const int b   = row >> 7;
    const int y   = row & 127;
    const int ocb = blockIdx.y << 7;

    // ldmatrix per-lane row addressing (byte offsets within a tile)
    const int l8   = lane & 7;                // row within 8-row matrix
    const int tsel = lane >> 3;               // matrix index 0..3
    // A tiles for warp-tile mt: rows wm*64+mt*16 + (tsel&1)*8 + l8, col (tsel>>1)*4
    uint32_t aoff[4];
    #pragma unroll
    for (int mt = 0; mt < 4; mt++)
        aoff[mt] = (uint32_t)(((wm * 64 + mt * 16 + (tsel & 1) * 8 + l8) * LDA
                               + (tsel >> 1) * 4) * 4);
    // B tiles for nt-pair p: rows wn*32 + (2p + (tsel>>1))*8 + l8, col (tsel&1)*4
    uint32_t boff[2];
    #pragma unroll
    for (int p = 0; p < 2; p++)
        boff[p] = (uint32_t)(((wn * 32 + (2 * p + (tsel >> 1)) * 8 + l8) * LDA
                              + (tsel & 1) * 4) * 4);

    float acc[4][4][4];
    #pragma unroll
    for (int mt = 0; mt < 4; mt++)
        #pragma unroll
        for (int nt = 0; nt < 4; nt++)
            #pragma unroll
            for (int i = 0; i < 4; i++) acc[mt][nt][i] = 0.f;

    // ---- async fill of one chunk (A: weights, B: im2col) into stage st
    auto issue_chunk = [&](int kb, int st) {
        const int ic0 = kb << 3;
        const uint32_t dA = sbase + st * STAGE;
        const uint32_t dB = dA + ATILE;
        #pragma unroll
        for (int it = 0; it < 18; it++) {
            const int v = tid + it * 256;       // 0..4607
            const int which = (v >= 2304);
            const int u  = which ? v - 2304 : v;
            const int r  = u / 18;              // oc (A) or pixel (B)
            const int k4 = u - r * 18;
            const int t  = k4 >> 1;             // tap 0..8
            const int g  = k4 & 1;              // ic float4 group (0/1)
            const uint32_t dst = (which ? dB : dA)
                               + (uint32_t)((r * LDA + t * 8 + g * 4) * 4);
            if (!which) {
                const float* src = wp + ((size_t)(t * OC + ocb + r)) * 128 + ic0 + g * 4;
                CP_ASYNC16(dst, src, 16);
            } else {
                const int gy = y + t / 3 - 1;
                const int gx = r + (t % 3) - 1;
                const bool ok = ((unsigned)gy < 128u) && ((unsigned)gx < 128u);
                const float* src = xT + (((size_t)b * 128 + (ok ? gy : 0)) * 128
                                         + (ok ? gx : 0)) * 128 + ic0 + g * 4;
                CP_ASYNC16(dst, src, ok ? 16 : 0);
            }
        }
        CP_COMMIT();
    };

    issue_chunk(0, 0);

    for (int kb = 0; kb < 16; kb++) {
        if (kb < 15) { issue_chunk(kb + 1, (kb + 1) & 1); CP_WAIT1(); }
        else         { CP_WAIT0(); }
        __syncthreads();

        const uint32_t sA = sbase + (kb & 1) * STAGE;
        const uint32_t sB = sA + ATILE;

        #pragma unroll
        for (int s = 0; s < 9; s++) {
            const uint32_t kbyte = (uint32_t)(s * 8 * 4);
            uint32_t af[4][4], bf[4][2];
            #pragma unroll
            for (int mt = 0; mt < 4; mt++)
                LDSM_X4(af[mt][0], af[mt][1], af[mt][2], af[mt][3],
                        sA + aoff[mt] + kbyte);
            #pragma unroll
            for (int p = 0; p < 2; p++)
                LDSM_X4(bf[2*p][0], bf[2*p][1], bf[2*p+1][0], bf[2*p+1][1],
                        sB + boff[p] + kbyte);
            #pragma unroll
            for (int mt = 0; mt < 4; mt++)
                #pragma unroll
                for (int nt = 0; nt < 4; nt++)
                    asm volatile(
                        "mma.sync.aligned.m16n8k8.row.col.f32.tf32.tf32.f32 "
                        "{%0,%1,%2,%3}, {%4,%5,%6,%7}, {%8,%9}, {%0,%1,%2,%3};"
                        : "+f"(acc[mt][nt][0]), "+f"(acc[mt][nt][1]),
                          "+f"(acc[mt][nt][2]), "+f"(acc[mt][nt][3])
                        : "r"(af[mt][0]), "r"(af[mt][1]), "r"(af[mt][2]), "r"(af[mt][3]),
                          "r"(bf[nt][0]), "r"(bf[nt][1]));
        }
        __syncthreads();   // buffer consumed before next issue overwrites it
    }

    // ---- epilogue: bias + relu into SMEM transpose buffer, coalesced store
    const int lr = lane >> 2;
    const int lc = lane & 3;
    float* s_t = (float*)smem;                // [oc][px], stride LDT
    #pragma unroll
    for (int mt = 0; mt < 4; mt++) {
        const int r0 = wm * 64 + mt * 16 + lr;
        const float bv0 = bias ? bias[ocb + r0]     : 0.f;
        const float bv1 = bias ? bias[ocb + r0 + 8] : 0.f;
        #pragma unroll
        for (int nt = 0; nt < 4; nt++) {
            const int c0 = wn * 32 + nt * 8 + 2 * lc;
            float v0 = acc[mt][nt][0] + bv0;
            float v1 = acc[mt][nt][1] + bv0;
            float v2 = acc[mt][nt][2] + bv1;
            float v3 = acc[mt][nt][3] + bv1;
            if (do_relu) {
                v0 = fmaxf(v0, 0.f); v1 = fmaxf(v1, 0.f);
                v2 = fmaxf(v2, 0.f); v3 = fmaxf(v3, 0.f);
            }
            *(float2*)(s_t + r0 * LDT + c0)       = make_float2(v0, v1);
            *(float2*)(s_t + (r0 + 8) * LDT + c0) = make_float2(v2, v3);
        }
    }
    __syncthreads();

    for (int idx = tid; idx < 128 * 32; idx += 256) {
        const int oc = idx >> 5;
        const int xg = idx & 31;
        float4 v = *(float4*)(s_t + oc * LDT + xg * 4);
        *(float4*)(out + ((size_t)b * OC + ocb + oc) * HWSZ + y * WW + xg * 4) = v;
    }
}

// ---------------------------------------------------------------------------
// Transpose (B,C,HW) -> (B,HW,C) with tf32 rounding.
// ---------------------------------------------------------------------------
__global__ void transpose_tf32_kernel(const float* __restrict__ in,
                                      float* __restrict__ outT)
{
    __shared__ float tile[32][33];
    const int b  = blockIdx.z;
    const int c0 = blockIdx.y << 5;
    const int q0 = blockIdx.x << 5;
    const int tx = threadIdx.x;          // 32
    const int ty = threadIdx.y;          // 8
    #pragma unroll
    for (int i = ty; i < 32; i += 8)
        tile[i][tx] = in[((size_t)b * CC + c0 + i) * HWSZ + q0 + tx];
    __syncthreads();
    #pragma unroll
    for (int j = ty; j < 32; j += 8)
        outT[((size_t)b * HWSZ + q0 + j) * CC + c0 + tx] = tf32r(tile[tx][j]);
}

// Pack weights (OC,128,3,3) -> (9,OC,128), tf32-rounded.
__global__ void pack_w_kernel(const float* __restrict__ w,
                              float* __restrict__ wpk, int OC)
{
    const int idx = blockIdx.x * 256 + threadIdx.x;
    if (idx >= OC * 128 * 9) return;
    const int oc = idx / (128 * 9);
    const int r  = idx - oc * (128 * 9);
    const int ic = r / 9;
    const int t  = r - ic * 9;
    wpk[((size_t)t * OC + oc) * 128 + ic] = tf32r(w[idx]);
}

// ---------------------------------------------------------------------------
// Fused deformable bilinear sampling + transpose: writes (B,H,W,C) tf32
// directly (quirky-reshape offset semantics preserved, sampling in fp32).
// ---------------------------------------------------------------------------
__global__ void deformT_kernel(const float* __restrict__ x,
                               const float* __restrict__ off,
                               float* __restrict__ xoT)
{
    __shared__ float tile[32][33];
    const int b  = blockIdx.z;
    const int c0 = blockIdx.y << 5;
    const int q0 = blockIdx.x << 5;
    const int tx = threadIdx.x;          // pixel within 32-block
    const int ty = threadIdx.y;          // 8

    #pragma unroll
    for (int i = ty; i < 32; i += 8) {
        const int c = c0 + i;
        const int q = q0 + tx;
        const int p = b * CC + c;
        const int pi = q >> 7;
        const int pj = q & 127;

        const float2 o2 = *(const float2*)(off + (size_t)p * 2 * HWSZ + 2 * q);
        float yc = fminf(fmaxf(o2.x + (float)pi, 0.f), 127.f);
        float xc = fminf(fmaxf(o2.y + (float)pj, 0.f), 127.f);
        float y0f = floorf(yc), y1f = ceilf(yc);
        float x0f = floorf(xc), x1f = ceilf(xc);
        int y0 = (int)y0f, y1 = (int)y1f;
        int x0 = (int)x0f, x1 = (int)x1f;

        const float* img = x + (size_t)p * HWSZ;
        float v_lt = img[y0 * WW + x0];
        float v_rb = img[y1 * WW + x1];
        float v_lb = img[y0 * WW + x1];
        float v_rt = img[y1 * WW + x0];

        float dy = yc - y0f;
        float dx = xc - x0f;
        float v_t = v_lt + (v_rt - v_lt) * dy;
        float v_b = v_lb + (v_rb - v_lb) * dy;
        tile[i][tx] = tf32r(v_t + (v_b - v_t) * dx);
    }
    __syncthreads();
    #pragma unroll
    for (int j = ty; j < 32; j += 8)
        xoT[((size_t)b * HWSZ + q0 + j) * CC + c0 + tx] = tile[tx][j];
}

// ---------------------------------------------------------------------------
// BatchNorm (training stats), deterministic 2-stage.
// ---------------------------------------------------------------------------
__global__ void bn_stats_kernel(const float* __restrict__ ych)
{
    const int c = blockIdx.x;
    const int b = blockIdx.y;
    const float* p = ych + ((size_t)b * CC + c) * HWSZ;
    float s = 0.f, s2 = 0.f;
    for (int q = threadIdx.x; q < HWSZ; q += 256) {
        float v = p[q];
        s += v; s2 += v * v;
    }
    __shared__ float rs[256], rs2[256];
    rs[threadIdx.x] = s; rs2[threadIdx.x] = s2;
    __syncthreads();
    for (int st = 128; st > 0; st >>= 1) {
        if (threadIdx.x < st) {
            rs[threadIdx.x]  += rs[threadIdx.x + st];
            rs2[threadIdx.x] += rs2[threadIdx.x + st];
        }
        __syncthreads();
    }
    if (threadIdx.x == 0) { g_part[c][b][0] = rs[0]; g_part[c][b][1] = rs2[0]; }
}

__global__ void bn_finalize_kernel(const float* __restrict__ gamma,
                                   const float* __restrict__ beta)
{
    const int c = threadIdx.x;
    float s = 0.f, s2 = 0.f;
    #pragma unroll
    for (int b = 0; b < BB; b++) { s += g_part[c][b][0]; s2 += g_part[c][b][1]; }
    const float n = (float)(BB * HWSZ);
    float mean = s / n;
    float var  = s2 / n - mean * mean;
    float sc   = gamma[c] * rsqrtf(var + 1e-5f);
    g_scale[c] = sc;
    g_shift[c] = beta[c] - mean * sc;
}

__global__ void bn_apply_kernel(float* __restrict__ ych)
{
    const int gid = blockIdx.x * 256 + threadIdx.x;
    const int c = (gid >> 14) & 127;
    ych[gid] = fmaf(ych[gid], g_scale[c], g_shift[c]);
}

// ---------------------------------------------------------------------------
extern "C" void kernel_launch(void* const* d_in, const int* in_sizes, int n_in,
                              void* d_out, int out_size)
{
    const float* x      = (const float*)d_in[0];
    const float* w_off  = (const float*)d_in[1];
    const float* w_conv = (const float*)d_in[2];
    const float* b_conv = (const float*)d_in[3];
    const float* gamma  = (const float*)d_in[4];
    const float* beta   = (const float*)d_in[5];
    float* out = (float*)d_out;

    float *off, *xT, *xoffT, *wp1, *wp2;
    cudaGetSymbolAddress((void**)&off,   g_off);
    cudaGetSymbolAddress((void**)&xT,    g_xT);
    cudaGetSymbolAddress((void**)&xoffT, g_xoffT);
    cudaGetSymbolAddress((void**)&wp1,   g_wp1);
    cudaGetSymbolAddress((void**)&wp2,   g_wp2);

    cudaFuncSetAttribute(conv_mma_kernel,
                         cudaFuncAttributeMaxDynamicSharedMemorySize, SMEM_TOTAL_CONV);

    // 0) transpose x -> xT (tf32), pack both weight tensors
    dim3 tg(HWSZ / 32, CC / 32, BB), tb(32, 8);
    transpose_tf32_kernel<<<tg, tb>>>(x, xT);
    pack_w_kernel<<<(256 * 128 * 9 + 255) / 256, 256>>>(w_off, wp1, 256);
    pack_w_kernel<<<(128 * 128 * 9 + 255) / 256, 256>>>(w_conv, wp2, 128);

    // 1) offsets = conv3x3(x, w_off), OC=256
    dim3 g1(BB * HH, 2);
    conv_mma_kernel<<<g1, 256, SMEM_TOTAL_CONV>>>(xT, wp1, nullptr, off, 256, 0);

    // 2) fused deformable sampling + transpose -> xoffT (tf32)
    deformT_kernel<<<tg, tb>>>(x, off, xoffT);

    // 3) y = relu(conv3x3(x_off, w_conv) + b_conv), OC=128 -> d_out
    dim3 g2(BB * HH, 1);
    conv_mma_kernel<<<g2, 256, SMEM_TOTAL_CONV>>>(xoffT, wp2, b_conv, out, 128, 1);

    // 4) batchnorm (training stats) in-place on d_out
    const int nelem = BB * CC * HWSZ;
    dim3 gs(CC, BB);
    bn_stats_kernel<<<gs, 256>>>(out);
    bn_finalize_kernel<<<1, CC>>>(gamma, beta);
    bn_apply_kernel<<<nelem / 256, 256>>>(out);
}

// round 6
// speedup vs baseline: 3.7100x; 1.4248x over previous
#include <cuda_runtime.h>
#include <cuda_bf16.h>
#include <cstdint>

// Problem constants
#define BB 8
#define CC 128
#define HH 128
#define WW 128
#define HWSZ (HH*WW)          // 16384

// Scratch (device globals: allocation-free)
__device__ float g_off  [(size_t)BB * 2 * CC * HWSZ];   // conv1 out (B,2C,H,W)
__device__ float g_xT   [(size_t)BB * HWSZ * CC];       // x    transposed (B,H,W,C), tf32
__device__ float g_xoffT[(size_t)BB * HWSZ * CC];       // deformed, transposed (B,H,W,C), tf32
__device__ float g_wp1  [(size_t)9 * 256 * 128];        // w_off  packed (t,oc,ic), tf32
__device__ float g_wp2  [(size_t)9 * 128 * 128];        // w_conv packed (t,oc,ic), tf32
__device__ float g_part[CC][BB][2];
__device__ float g_scale[CC];
__device__ float g_shift[CC];

__device__ __forceinline__ float tf32r(float v) {
    float r;
    asm("cvt.rna.tf32.f32 %0, %1;" : "=f"(r) : "f"(v));
    return r;
}
__device__ __forceinline__ uint32_t smem_u32(const void* p) {
    uint32_t a;
    asm("{ .reg .u64 t; cvta.to.shared.u64 t, %1; cvt.u32.u64 %0, t; }"
        : "=r"(a) : "l"(p));
    return a;
}
#define CP_ASYNC16(dst, src, sz) \
    asm volatile("cp.async.cg.shared.global [%0], [%1], 16, %2;" \
                 :: "r"(dst), "l"(src), "r"(sz))
#define CP_COMMIT()  asm volatile("cp.async.commit_group;")
#define CP_WAIT0()   asm volatile("cp.async.wait_group 0;")
#define LDSM_X4(r0, r1, r2, r3, addr) \
    asm volatile("ldmatrix.sync.aligned.m8n8.x4.shared.b16 {%0,%1,%2,%3}, [%4];" \
                 : "=r"(r0), "=r"(r1), "=r"(r2), "=r"(r3) : "r"(addr))

// ---------------------------------------------------------------------------
// Implicit-GEMM conv 3x3 via warp-level tf32 mma.sync.
// CTA: D[128 oc x 256 px] (TWO image rows y0, y0+1), oc block ocb.
// K = 1152 = 9 taps x 128 ic; 18 chunks of one half-tap (64 ic) each ->
// constant (dy,dx) shift per chunk, 8 k8-steps per chunk.
// 8 warps as 2 (m) x 4 (n); warp tile 64 oc x 64 px; m16n8k8 fragments via
// ldmatrix. SMEM row stride LDA=68 floats (row-start banks 4r mod 32 ->
// 8 disjoint 4-bank groups; ldmatrix conflict-free).
// cp.async 2-stage pipeline, ONE __syncthreads per chunk.
// ---------------------------------------------------------------------------
#define LDA    68
#define ATILE  (128 * LDA * 4)              // 34816 B
#define BTILE  (256 * LDA * 4)              // 69632 B
#define STAGE  (ATILE + BTILE)              // 104448 B
#define SMEM_TOTAL_CONV (2 * STAGE)         // 208896 B
#define LDT    260                          // epilogue transpose stride (floats)

__global__ void __launch_bounds__(256, 1)
conv_mma_kernel(const float* __restrict__ xT,   // (B,H,W,C) tf32
                const float* __restrict__ wp,   // (9,OC,128) tf32
                const float* __restrict__ bias, // (OC,) or nullptr
                float* __restrict__ out,        // (B,OC,H,W)
                int OC, int do_relu)
{
    extern __shared__ char smem[];
    const uint32_t sbase = smem_u32(smem);

    const int tid  = threadIdx.x;
    const int wid  = tid >> 5;
    const int lane = tid & 31;
    const int wm   = wid & 1;                 // warp m (2): 64 oc each
    const int wn   = wid >> 1;                // warp n (4): 64 px each

    const int row = blockIdx.x;               // 0 .. BB*HH/2-1
    const int b   = row >> 6;
    const int y0  = (row & 63) << 1;          // two rows y0, y0+1
    const int ocb = blockIdx.y << 7;

    // ldmatrix per-lane addressing (byte offsets within a tile)
    const int l8   = lane & 7;
    const int tsel = lane >> 3;               // matrix index 0..3
    uint32_t aoff[4];
    #pragma unroll
    for (int mt = 0; mt < 4; mt++)
        aoff[mt] = (uint32_t)(((wm * 64 + mt * 16 + (tsel & 1) * 8 + l8) * LDA
                               + (tsel >> 1) * 4) * 4);
    uint32_t boff[4];
    #pragma unroll
    for (int p = 0; p < 4; p++)
        boff[p] = (uint32_t)(((wn * 64 + (2 * p + (tsel >> 1)) * 8 + l8) * LDA
                              + (tsel & 1) * 4) * 4);

    float acc[4][8][4];
    #pragma unroll
    for (int mt = 0; mt < 4; mt++)
        #pragma unroll
        for (int nt = 0; nt < 8; nt++)
            #pragma unroll
            for (int i = 0; i < 4; i++) acc[mt][nt][i] = 0.f;

    // ---- async fill of one chunk into stage st. chunk kb: tap=kb>>1, ic half
    auto issue_chunk = [&](int kb, int st) {
        const int t   = kb >> 1;
        const int ic0 = (kb & 1) << 6;
        const int dy  = t / 3 - 1;
        const int dx  = t % 3 - 1;
        const uint32_t dA = sbase + st * STAGE;
        const uint32_t dB = dA + ATILE;
        // A: 128 oc x 64 ic = 2048 float4 (8 per thread)
        #pragma unroll
        for (int i = 0; i < 8; i++) {
            const int v = tid + i * 256;
            const int r = v >> 4;             // oc 0..127
            const int g = v & 15;             // ic float4 group
            const float* src = wp + ((size_t)(t * OC + ocb + r)) * 128 + ic0 + g * 4;
            CP_ASYNC16(dA + (uint32_t)(r * (LDA * 4) + g * 16), src, 16);
        }
        // B: 256 px x 64 ic = 4096 float4 (16 per thread)
        #pragma unroll
        for (int i = 0; i < 16; i++) {
            const int u = tid + i * 256;
            const int r = u >> 4;             // pixel 0..255
            const int g = u & 15;
            const int gy = y0 + (r >> 7) + dy;
            const int gx = (r & 127) + dx;
            const bool ok = ((unsigned)gy < 128u) && ((unsigned)gx < 128u);
            const float* src = xT + (((size_t)b * 128 + (ok ? gy : 0)) * 128
                                     + (ok ? gx : 0)) * 128 + ic0 + g * 4;
            CP_ASYNC16(dB + (uint32_t)(r * (LDA * 4) + g * 16), src, ok ? 16 : 0);
        }
        CP_COMMIT();
    };

    issue_chunk(0, 0);

    for (int kb = 0; kb < 18; kb++) {
        CP_WAIT0();
        __syncthreads();                     // fills of kb visible; computes of
                                             // kb-1 done -> safe to overwrite
        if (kb < 17) issue_chunk(kb + 1, (kb + 1) & 1);

        const uint32_t sA = sbase + (kb & 1) * STAGE;
        const uint32_t sB = sA + ATILE;

        #pragma unroll
        for (int s = 0; s < 8; s++) {
            const uint32_t kbyte = (uint32_t)(s * 32);
            uint32_t af[4][4], bf[8][2];
            #pragma unroll
            for (int mt = 0; mt < 4; mt++)
                LDSM_X4(af[mt][0], af[mt][1], af[mt][2], af[mt][3],
                        sA + aoff[mt] + kbyte);
            #pragma unroll
            for (int p = 0; p < 4; p++)
                LDSM_X4(bf[2*p][0], bf[2*p][1], bf[2*p+1][0], bf[2*p+1][1],
                        sB + boff[p] + kbyte);
            #pragma unroll
            for (int mt = 0; mt < 4; mt++)
                #pragma unroll
                for (int nt = 0; nt < 8; nt++)
                    asm volatile(
                        "mma.sync.aligned.m16n8k8.row.col.f32.tf32.tf32.f32 "
                        "{%0,%1,%2,%3}, {%4,%5,%6,%7}, {%8,%9}, {%0,%1,%2,%3};"
                        : "+f"(acc[mt][nt][0]), "+f"(acc[mt][nt][1]),
                          "+f"(acc[mt][nt][2]), "+f"(acc[mt][nt][3])
                        : "r"(af[mt][0]), "r"(af[mt][1]), "r"(af[mt][2]), "r"(af[mt][3]),
                          "r"(bf[nt][0]), "r"(bf[nt][1]));
        }
    }

    // ---- epilogue: bias + relu into SMEM transpose buffer, coalesced store
    __syncthreads();
    const int lr = lane >> 2;
    const int lc = lane & 3;
    float* s_t = (float*)smem;                // [oc][px], stride LDT
    #pragma unroll
    for (int mt = 0; mt < 4; mt++) {
        const int r0 = wm * 64 + mt * 16 + lr;
        const float bv0 = bias ? bias[ocb + r0]     : 0.f;
        const float bv1 = bias ? bias[ocb + r0 + 8] : 0.f;
        #pragma unroll
        for (int nt = 0; nt < 8; nt++) {
            const int c0 = wn * 64 + nt * 8 + 2 * lc;
            float v0 = acc[mt][nt][0] + bv0;
            float v1 = acc[mt][nt][1] + bv0;
            float v2 = acc[mt][nt][2] + bv1;
            float v3 = acc[mt][nt][3] + bv1;
            if (do_relu) {
                v0 = fmaxf(v0, 0.f); v1 = fmaxf(v1, 0.f);
                v2 = fmaxf(v2, 0.f); v3 = fmaxf(v3, 0.f);
            }
            *(float2*)(s_t + r0 * LDT + c0)       = make_float2(v0, v1);
            *(float2*)(s_t + (r0 + 8) * LDT + c0) = make_float2(v2, v3);
        }
    }
    __syncthreads();

    for (int idx = tid; idx < 128 * 64; idx += 256) {
        const int oc = idx >> 6;
        const int xg = idx & 63;              // float4 group over 256 px
        const int py = y0 + (xg >> 5);
        const int col = (xg & 31) << 2;
        float4 v = *(float4*)(s_t + oc * LDT + xg * 4);
        *(float4*)(out + ((size_t)b * OC + ocb + oc) * HWSZ + py * WW + col) = v;
    }
}

// ---------------------------------------------------------------------------
// Transpose (B,C,HW) -> (B,HW,C) with tf32 rounding.
// ---------------------------------------------------------------------------
__global__ void transpose_tf32_kernel(const float* __restrict__ in,
                                      float* __restrict__ outT)
{
    __shared__ float tile[32][33];
    const int b  = blockIdx.z;
    const int c0 = blockIdx.y << 5;
    const int q0 = blockIdx.x << 5;
    const int tx = threadIdx.x;          // 32
    const int ty = threadIdx.y;          // 8
    #pragma unroll
    for (int i = ty; i < 32; i += 8)
        tile[i][tx] = in[((size_t)b * CC + c0 + i) * HWSZ + q0 + tx];
    __syncthreads();
    #pragma unroll
    for (int j = ty; j < 32; j += 8)
        outT[((size_t)b * HWSZ + q0 + j) * CC + c0 + tx] = tf32r(tile[tx][j]);
}

// Pack weights (OC,128,3,3) -> (9,OC,128), tf32-rounded.
__global__ void pack_w_kernel(const float* __restrict__ w,
                              float* __restrict__ wpk, int OC)
{
    const int idx = blockIdx.x * 256 + threadIdx.x;
    if (idx >= OC * 128 * 9) return;
    const int oc = idx / (128 * 9);
    const int r  = idx - oc * (128 * 9);
    const int ic = r / 9;
    const int t  = r - ic * 9;
    wpk[((size_t)t * OC + oc) * 128 + ic] = tf32r(w[idx]);
}

// ---------------------------------------------------------------------------
// Fused deformable bilinear sampling + transpose: writes (B,H,W,C) tf32
// directly (quirky-reshape offset semantics preserved, sampling in fp32).
// ---------------------------------------------------------------------------
__global__ void deformT_kernel(const float* __restrict__ x,
                               const float* __restrict__ off,
                               float* __restrict__ xoT)
{
    __shared__ float tile[32][33];
    const int b  = blockIdx.z;
    const int c0 = blockIdx.y << 5;
    const int q0 = blockIdx.x << 5;
    const int tx = threadIdx.x;
    const int ty = threadIdx.y;

    #pragma unroll
    for (int i = ty; i < 32; i += 8) {
        const int c = c0 + i;
        const int q = q0 + tx;
        const int p = b * CC + c;
        const int pi = q >> 7;
        const int pj = q & 127;

        const float2 o2 = *(const float2*)(off + (size_t)p * 2 * HWSZ + 2 * q);
        float yc = fminf(fmaxf(o2.x + (float)pi, 0.f), 127.f);
        float xc = fminf(fmaxf(o2.y + (float)pj, 0.f), 127.f);
        float y0f = floorf(yc), y1f = ceilf(yc);
        float x0f = floorf(xc), x1f = ceilf(xc);
        int y0 = (int)y0f, y1 = (int)y1f;
        int x0 = (int)x0f, x1 = (int)x1f;

        const float* img = x + (size_t)p * HWSZ;
        float v_lt = img[y0 * WW + x0];
        float v_rb = img[y1 * WW + x1];
        float v_lb = img[y0 * WW + x1];
        float v_rt = img[y1 * WW + x0];

        float dy = yc - y0f;
        float dx = xc - x0f;
        float v_t = v_lt + (v_rt - v_lt) * dy;
        float v_b = v_lb + (v_rb - v_lb) * dy;
        tile[i][tx] = tf32r(v_t + (v_b - v_t) * dx);
    }
    __syncthreads();
    #pragma unroll
    for (int j = ty; j < 32; j += 8)
        xoT[((size_t)b * HWSZ + q0 + j) * CC + c0 + tx] = tile[tx][j];
}

// ---------------------------------------------------------------------------
// BatchNorm (training stats), deterministic 2-stage.
// ---------------------------------------------------------------------------
__global__ void bn_stats_kernel(const float* __restrict__ ych)
{
    const int c = blockIdx.x;
    const int b = blockIdx.y;
    const float* p = ych + ((size_t)b * CC + c) * HWSZ;
    float s = 0.f, s2 = 0.f;
    for (int q = threadIdx.x; q < HWSZ; q += 256) {
        float v = p[q];
        s += v; s2 += v * v;
    }
    __shared__ float rs[256], rs2[256];
    rs[threadIdx.x] = s; rs2[threadIdx.x] = s2;
    __syncthreads();
    for (int st = 128; st > 0; st >>= 1) {
        if (threadIdx.x < st) {
            rs[threadIdx.x]  += rs[threadIdx.x + st];
            rs2[threadIdx.x] += rs2[threadIdx.x + st];
        }
        __syncthreads();
    }
    if (threadIdx.x == 0) { g_part[c][b][0] = rs[0]; g_part[c][b][1] = rs2[0]; }
}

__global__ void bn_finalize_kernel(const float* __restrict__ gamma,
                                   const float* __restrict__ beta)
{
    const int c = threadIdx.x;
    float s = 0.f, s2 = 0.f;
    #pragma unroll
    for (int b = 0; b < BB; b++) { s += g_part[c][b][0]; s2 += g_part[c][b][1]; }
    const float n = (float)(BB * HWSZ);
    float mean = s / n;
    float var  = s2 / n - mean * mean;
    float sc   = gamma[c] * rsqrtf(var + 1e-5f);
    g_scale[c] = sc;
    g_shift[c] = beta[c] - mean * sc;
}

__global__ void bn_apply_kernel(float* __restrict__ ych)
{
    const int gid = blockIdx.x * 256 + threadIdx.x;
    const int c = (gid >> 14) & 127;
    ych[gid] = fmaf(ych[gid], g_scale[c], g_shift[c]);
}

// ---------------------------------------------------------------------------
extern "C" void kernel_launch(void* const* d_in, const int* in_sizes, int n_in,
                              void* d_out, int out_size)
{
    const float* x      = (const float*)d_in[0];
    const float* w_off  = (const float*)d_in[1];
    const float* w_conv = (const float*)d_in[2];
    const float* b_conv = (const float*)d_in[3];
    const float* gamma  = (const float*)d_in[4];
    const float* beta   = (const float*)d_in[5];
    float* out = (float*)d_out;

    float *off, *xT, *xoffT, *wp1, *wp2;
    cudaGetSymbolAddress((void**)&off,   g_off);
    cudaGetSymbolAddress((void**)&xT,    g_xT);
    cudaGetSymbolAddress((void**)&xoffT, g_xoffT);
    cudaGetSymbolAddress((void**)&wp1,   g_wp1);
    cudaGetSymbolAddress((void**)&wp2,   g_wp2);

    cudaFuncSetAttribute(conv_mma_kernel,
                         cudaFuncAttributeMaxDynamicSharedMemorySize, SMEM_TOTAL_CONV);

    // 0) transpose x -> xT (tf32), pack both weight tensors
    dim3 tg(HWSZ / 32, CC / 32, BB), tb(32, 8);
    transpose_tf32_kernel<<<tg, tb>>>(x, xT);
    pack_w_kernel<<<(256 * 128 * 9 + 255) / 256, 256>>>(w_off, wp1, 256);
    pack_w_kernel<<<(128 * 128 * 9 + 255) / 256, 256>>>(w_conv, wp2, 128);

    // 1) offsets = conv3x3(x, w_off), OC=256
    dim3 g1(BB * HH / 2, 2);
    conv_mma_kernel<<<g1, 256, SMEM_TOTAL_CONV>>>(xT, wp1, nullptr, off, 256, 0);

    // 2) fused deformable sampling + transpose -> xoffT (tf32)
    deformT_kernel<<<tg, tb>>>(x, off, xoffT);

    // 3) y = relu(conv3x3(x_off, w_conv) + b_conv), OC=128 -> d_out
    dim3 g2(BB * HH / 2, 1);
    conv_mma_kernel<<<g2, 256, SMEM_TOTAL_CONV>>>(xoffT, wp2, b_conv, out, 128, 1);

    // 4) batchnorm (training stats) in-place on d_out
    const int nelem = BB * CC * HWSZ;
    dim3 gs(CC, BB);
    bn_stats_kernel<<<gs, 256>>>(out);
    bn_finalize_kernel<<<1, CC>>>(gamma, beta);
    bn_apply_kernel<<<nelem / 256, 256>>>(out);
}

// round 7
// speedup vs baseline: 3.8521x; 1.0383x over previous
#include <cuda_runtime.h>
#include <cuda_bf16.h>
#include <cstdint>

// Problem constants
#define BB 8
#define CC 128
#define HH 128
#define WW 128
#define HWSZ (HH*WW)          // 16384

// Scratch (device globals: allocation-free)
__device__ float g_off  [(size_t)BB * 2 * CC * HWSZ];   // conv1 out (B,2C,H,W)
__device__ float g_xT   [(size_t)BB * HWSZ * CC];       // x    transposed (B,H,W,C), tf32
__device__ float g_xoffT[(size_t)BB * HWSZ * CC];       // deformed, transposed (B,H,W,C), tf32
__device__ float g_wp1  [(size_t)9 * 256 * 128];        // w_off  packed (t,oc,ic), tf32
__device__ float g_wp2  [(size_t)9 * 128 * 128];        // w_conv packed (t,oc,ic), tf32
__device__ float g_part[CC][BB][2];
__device__ float g_scale[CC];
__device__ float g_shift[CC];

__device__ __forceinline__ float tf32r(float v) {
    float r;
    asm("cvt.rna.tf32.f32 %0, %1;" : "=f"(r) : "f"(v));
    return r;
}
__device__ __forceinline__ uint32_t smem_u32(const void* p) {
    uint32_t a;
    asm("{ .reg .u64 t; cvta.to.shared.u64 t, %1; cvt.u32.u64 %0, t; }"
        : "=r"(a) : "l"(p));
    return a;
}
#define CP_ASYNC16(dst, src, sz) \
    asm volatile("cp.async.cg.shared.global [%0], [%1], 16, %2;" \
                 :: "r"(dst), "l"(src), "r"(sz))
#define CP_COMMIT()  asm volatile("cp.async.commit_group;")
#define CP_WAIT0()   asm volatile("cp.async.wait_group 0;")
#define LDSM_X4(r0, r1, r2, r3, addr) \
    asm volatile("ldmatrix.sync.aligned.m8n8.x4.shared.b16 {%0,%1,%2,%3}, [%4];" \
                 : "=r"(r0), "=r"(r1), "=r"(r2), "=r"(r3) : "r"(addr))

// ---------------------------------------------------------------------------
// Implicit-GEMM conv 3x3 via warp-level tf32 mma.sync.
// CTA: D[128 oc x 256 px] (TWO image rows y0, y0+1), oc block ocb.
// K = 1152 = 9 taps x 128 ic; 18 chunks of one half-tap (64 ic) each ->
// constant (dy,dx) shift per chunk, 8 k8-steps per chunk.
// 512 threads / 16 warps as 2 (m) x 8 (n); warp tile 64 oc x 32 px ->
// 4 warps/SMSP for latency hiding, acc = 64 regs/thread.
// m16n8k8 fragments via ldmatrix; LDA=68 floats (conflict-free).
// cp.async 2-stage pipeline, ONE __syncthreads per chunk.
// ---------------------------------------------------------------------------
#define NTHR   512
#define LDA    68
#define ATILE  (128 * LDA * 4)              // 34816 B
#define BTILE  (256 * LDA * 4)              // 69632 B
#define STAGE  (ATILE + BTILE)              // 104448 B
#define SMEM_TOTAL_CONV (2 * STAGE)         // 208896 B
#define LDT    260                          // epilogue transpose stride (floats)

__global__ void __launch_bounds__(NTHR, 1)
conv_mma_kernel(const float* __restrict__ xT,   // (B,H,W,C) tf32
                const float* __restrict__ wp,   // (9,OC,128) tf32
                const float* __restrict__ bias, // (OC,) or nullptr
                float* __restrict__ out,        // (B,OC,H,W)
                int OC, int do_relu)
{
    extern __shared__ char smem[];
    const uint32_t sbase = smem_u32(smem);

    const int tid  = threadIdx.x;
    const int wid  = tid >> 5;
    const int lane = tid & 31;
    const int wm   = wid & 1;                 // warp m (2): 64 oc each
    const int wn   = wid >> 1;                // warp n (8): 32 px each

    const int row = blockIdx.x;               // 0 .. BB*HH/2-1
    const int b   = row >> 6;
    const int y0  = (row & 63) << 1;          // two rows y0, y0+1
    const int ocb = blockIdx.y << 7;

    // ldmatrix per-lane addressing (byte offsets within a tile)
    const int l8   = lane & 7;
    const int tsel = lane >> 3;               // matrix index 0..3
    uint32_t aoff[4];
    #pragma unroll
    for (int mt = 0; mt < 4; mt++)
        aoff[mt] = (uint32_t)(((wm * 64 + mt * 16 + (tsel & 1) * 8 + l8) * LDA
                               + (tsel >> 1) * 4) * 4);
    uint32_t boff[2];
    #pragma unroll
    for (int p = 0; p < 2; p++)
        boff[p] = (uint32_t)(((wn * 32 + (2 * p + (tsel >> 1)) * 8 + l8) * LDA
                              + (tsel & 1) * 4) * 4);

    float acc[4][4][4];
    #pragma unroll
    for (int mt = 0; mt < 4; mt++)
        #pragma unroll
        for (int nt = 0; nt < 4; nt++)
            #pragma unroll
            for (int i = 0; i < 4; i++) acc[mt][nt][i] = 0.f;

    // ---- async fill of one chunk into stage st. chunk kb: tap=kb>>1, ic half
    auto issue_chunk = [&](int kb, int st) {
        const int t   = kb >> 1;
        const int ic0 = (kb & 1) << 6;
        const int dy  = t / 3 - 1;
        const int dx  = t % 3 - 1;
        const uint32_t dA = sbase + st * STAGE;
        const uint32_t dB = dA + ATILE;
        // A: 128 oc x 64 ic = 2048 float4 (4 per thread)
        #pragma unroll
        for (int i = 0; i < 4; i++) {
            const int v = tid + i * NTHR;
            const int r = v >> 4;             // oc 0..127
            const int g = v & 15;             // ic float4 group
            const float* src = wp + ((size_t)(t * OC + ocb + r)) * 128 + ic0 + g * 4;
            CP_ASYNC16(dA + (uint32_t)(r * (LDA * 4) + g * 16), src, 16);
        }
        // B: 256 px x 64 ic = 4096 float4 (8 per thread)
        #pragma unroll
        for (int i = 0; i < 8; i++) {
            const int u = tid + i * NTHR;
            const int r = u >> 4;             // pixel 0..255
            const int g = u & 15;
            const int gy = y0 + (r >> 7) + dy;
            const int gx = (r & 127) + dx;
            const bool ok = ((unsigned)gy < 128u) && ((unsigned)gx < 128u);
            const float* src = xT + (((size_t)b * 128 + (ok ? gy : 0)) * 128
                                     + (ok ? gx : 0)) * 128 + ic0 + g * 4;
            CP_ASYNC16(dB + (uint32_t)(r * (LDA * 4) + g * 16), src, ok ? 16 : 0);
        }
        CP_COMMIT();
    };

    issue_chunk(0, 0);

    for (int kb = 0; kb < 18; kb++) {
        CP_WAIT0();
        __syncthreads();                     // fills of kb visible; computes of
                                             // kb-1 done -> safe to overwrite
        if (kb < 17) issue_chunk(kb + 1, (kb + 1) & 1);

        const uint32_t sA = sbase + (kb & 1) * STAGE;
        const uint32_t sB = sA + ATILE;

        #pragma unroll
        for (int s = 0; s < 8; s++) {
            const uint32_t kbyte = (uint32_t)(s * 32);
            uint32_t af[4][4], bf[4][2];
            #pragma unroll
            for (int mt = 0; mt < 4; mt++)
                LDSM_X4(af[mt][0], af[mt][1], af[mt][2], af[mt][3],
                        sA + aoff[mt] + kbyte);
            #pragma unroll
            for (int p = 0; p < 2; p++)
                LDSM_X4(bf[2*p][0], bf[2*p][1], bf[2*p+1][0], bf[2*p+1][1],
                        sB + boff[p] + kbyte);
            #pragma unroll
            for (int mt = 0; mt < 4; mt++)
                #pragma unroll
                for (int nt = 0; nt < 4; nt++)
                    asm volatile(
                        "mma.sync.aligned.m16n8k8.row.col.f32.tf32.tf32.f32 "
                        "{%0,%1,%2,%3}, {%4,%5,%6,%7}, {%8,%9}, {%0,%1,%2,%3};"
                        : "+f"(acc[mt][nt][0]), "+f"(acc[mt][nt][1]),
                          "+f"(acc[mt][nt][2]), "+f"(acc[mt][nt][3])
                        : "r"(af[mt][0]), "r"(af[mt][1]), "r"(af[mt][2]), "r"(af[mt][3]),
                          "r"(bf[nt][0]), "r"(bf[nt][1]));
        }
    }

    // ---- epilogue: bias + relu into SMEM transpose buffer, coalesced store
    __syncthreads();
    const int lr = lane >> 2;
    const int lc = lane & 3;
    float* s_t = (float*)smem;                // [oc][px], stride LDT
    #pragma unroll
    for (int mt = 0; mt < 4; mt++) {
        const int r0 = wm * 64 + mt * 16 + lr;
        const float bv0 = bias ? bias[ocb + r0]     : 0.f;
        const float bv1 = bias ? bias[ocb + r0 + 8] : 0.f;
        #pragma unroll
        for (int nt = 0; nt < 4; nt++) {
            const int c0 = wn * 32 + nt * 8 + 2 * lc;
            float v0 = acc[mt][nt][0] + bv0;
            float v1 = acc[mt][nt][1] + bv0;
            float v2 = acc[mt][nt][2] + bv1;
            float v3 = acc[mt][nt][3] + bv1;
            if (do_relu) {
                v0 = fmaxf(v0, 0.f); v1 = fmaxf(v1, 0.f);
                v2 = fmaxf(v2, 0.f); v3 = fmaxf(v3, 0.f);
            }
            *(float2*)(s_t + r0 * LDT + c0)       = make_float2(v0, v1);
            *(float2*)(s_t + (r0 + 8) * LDT + c0) = make_float2(v2, v3);
        }
    }
    __syncthreads();

    for (int idx = tid; idx < 128 * 64; idx += NTHR) {
        const int oc = idx >> 6;
        const int xg = idx & 63;              // float4 group over 256 px
        const int py = y0 + (xg >> 5);
        const int col = (xg & 31) << 2;
        float4 v = *(float4*)(s_t + oc * LDT + xg * 4);
        *(float4*)(out + ((size_t)b * OC + ocb + oc) * HWSZ + py * WW + col) = v;
    }
}

// ---------------------------------------------------------------------------
// Transpose (B,C,HW) -> (B,HW,C) with tf32 rounding.
// ---------------------------------------------------------------------------
__global__ void transpose_tf32_kernel(const float* __restrict__ in,
                                      float* __restrict__ outT)
{
    __shared__ float tile[32][33];
    const int b  = blockIdx.z;
    const int c0 = blockIdx.y << 5;
    const int q0 = blockIdx.x << 5;
    const int tx = threadIdx.x;          // 32
    const int ty = threadIdx.y;          // 8
    #pragma unroll
    for (int i = ty; i < 32; i += 8)
        tile[i][tx] = in[((size_t)b * CC + c0 + i) * HWSZ + q0 + tx];
    __syncthreads();
    #pragma unroll
    for (int j = ty; j < 32; j += 8)
        outT[((size_t)b * HWSZ + q0 + j) * CC + c0 + tx] = tf32r(tile[tx][j]);
}

// Pack weights (OC,128,3,3) -> (9,OC,128), tf32-rounded.
__global__ void pack_w_kernel(const float* __restrict__ w,
                              float* __restrict__ wpk, int OC)
{
    const int idx = blockIdx.x * 256 + threadIdx.x;
    if (idx >= OC * 128 * 9) return;
    const int oc = idx / (128 * 9);
    const int r  = idx - oc * (128 * 9);
    const int ic = r / 9;
    const int t  = r - ic * 9;
    wpk[((size_t)t * OC + oc) * 128 + ic] = tf32r(w[idx]);
}

// ---------------------------------------------------------------------------
// Fused deformable bilinear sampling + transpose: writes (B,H,W,C) tf32
// directly (quirky-reshape offset semantics preserved, sampling in fp32).
// ---------------------------------------------------------------------------
__global__ void deformT_kernel(const float* __restrict__ x,
                               const float* __restrict__ off,
                               float* __restrict__ xoT)
{
    __shared__ float tile[32][33];
    const int b  = blockIdx.z;
    const int c0 = blockIdx.y << 5;
    const int q0 = blockIdx.x << 5;
    const int tx = threadIdx.x;
    const int ty = threadIdx.y;

    #pragma unroll
    for (int i = ty; i < 32; i += 8) {
        const int c = c0 + i;
        const int q = q0 + tx;
        const int p = b * CC + c;
        const int pi = q >> 7;
        const int pj = q & 127;

        const float2 o2 = *(const float2*)(off + (size_t)p * 2 * HWSZ + 2 * q);
        float yc = fminf(fmaxf(o2.x + (float)pi, 0.f), 127.f);
        float xc = fminf(fmaxf(o2.y + (float)pj, 0.f), 127.f);
        float y0f = floorf(yc), y1f = ceilf(yc);
        float x0f = floorf(xc), x1f = ceilf(xc);
        int y0 = (int)y0f, y1 = (int)y1f;
        int x0 = (int)x0f, x1 = (int)x1f;

        const float* img = x + (size_t)p * HWSZ;
        float v_lt = img[y0 * WW + x0];
        float v_rb = img[y1 * WW + x1];
        float v_lb = img[y0 * WW + x1];
        float v_rt = img[y1 * WW + x0];

        float dy = yc - y0f;
        float dx = xc - x0f;
        float v_t = v_lt + (v_rt - v_lt) * dy;
        float v_b = v_lb + (v_rb - v_lb) * dy;
        tile[i][tx] = tf32r(v_t + (v_b - v_t) * dx);
    }
    __syncthreads();
    #pragma unroll
    for (int j = ty; j < 32; j += 8)
        xoT[((size_t)b * HWSZ + q0 + j) * CC + c0 + tx] = tile[tx][j];
}

// ---------------------------------------------------------------------------
// BatchNorm (training stats), deterministic 2-stage.
// ---------------------------------------------------------------------------
__global__ void bn_stats_kernel(const float* __restrict__ ych)
{
    const int c = blockIdx.x;
    const int b = blockIdx.y;
    const float* p = ych + ((size_t)b * CC + c) * HWSZ;
    float s = 0.f, s2 = 0.f;
    for (int q = threadIdx.x; q < HWSZ; q += 256) {
        float v = p[q];
        s += v; s2 += v * v;
    }
    __shared__ float rs[256], rs2[256];
    rs[threadIdx.x] = s; rs2[threadIdx.x] = s2;
    __syncthreads();
    for (int st = 128; st > 0; st >>= 1) {
        if (threadIdx.x < st) {
            rs[threadIdx.x]  += rs[threadIdx.x + st];
            rs2[threadIdx.x] += rs2[threadIdx.x + st];
        }
        __syncthreads();
    }
    if (threadIdx.x == 0) { g_part[c][b][0] = rs[0]; g_part[c][b][1] = rs2[0]; }
}

__global__ void bn_finalize_kernel(const float* __restrict__ gamma,
                                   const float* __restrict__ beta)
{
    const int c = threadIdx.x;
    float s = 0.f, s2 = 0.f;
    #pragma unroll
    for (int b = 0; b < BB; b++) { s += g_part[c][b][0]; s2 += g_part[c][b][1]; }
    const float n = (float)(BB * HWSZ);
    float mean = s / n;
    float var  = s2 / n - mean * mean;
    float sc   = gamma[c] * rsqrtf(var + 1e-5f);
    g_scale[c] = sc;
    g_shift[c] = beta[c] - mean * sc;
}

__global__ void bn_apply_kernel(float* __restrict__ ych)
{
    const int gid = blockIdx.x * 256 + threadIdx.x;
    const int c = (gid >> 14) & 127;
    ych[gid] = fmaf(ych[gid], g_scale[c], g_shift[c]);
}

// ---------------------------------------------------------------------------
extern "C" void kernel_launch(void* const* d_in, const int* in_sizes, int n_in,
                              void* d_out, int out_size)
{
    const float* x      = (const float*)d_in[0];
    const float* w_off  = (const float*)d_in[1];
    const float* w_conv = (const float*)d_in[2];
    const float* b_conv = (const float*)d_in[3];
    const float* gamma  = (const float*)d_in[4];
    const float* beta   = (const float*)d_in[5];
    float* out = (float*)d_out;

    float *off, *xT, *xoffT, *wp1, *wp2;
    cudaGetSymbolAddress((void**)&off,   g_off);
    cudaGetSymbolAddress((void**)&xT,    g_xT);
    cudaGetSymbolAddress((void**)&xoffT, g_xoffT);
    cudaGetSymbolAddress((void**)&wp1,   g_wp1);
    cudaGetSymbolAddress((void**)&wp2,   g_wp2);

    cudaFuncSetAttribute(conv_mma_kernel,
                         cudaFuncAttributeMaxDynamicSharedMemorySize, SMEM_TOTAL_CONV);

    // 0) transpose x -> xT (tf32), pack both weight tensors
    dim3 tg(HWSZ / 32, CC / 32, BB), tb(32, 8);
    transpose_tf32_kernel<<<tg, tb>>>(x, xT);
    pack_w_kernel<<<(256 * 128 * 9 + 255) / 256, 256>>>(w_off, wp1, 256);
    pack_w_kernel<<<(128 * 128 * 9 + 255) / 256, 256>>>(w_conv, wp2, 128);

    // 1) offsets = conv3x3(x, w_off), OC=256
    dim3 g1(BB * HH / 2, 2);
    conv_mma_kernel<<<g1, NTHR, SMEM_TOTAL_CONV>>>(xT, wp1, nullptr, off, 256, 0);

    // 2) fused deformable sampling + transpose -> xoffT (tf32)
    deformT_kernel<<<tg, tb>>>(x, off, xoffT);

    // 3) y = relu(conv3x3(x_off, w_conv) + b_conv), OC=128 -> d_out
    dim3 g2(BB * HH / 2, 1);
    conv_mma_kernel<<<g2, NTHR, SMEM_TOTAL_CONV>>>(xoffT, wp2, b_conv, out, 128, 1);

    // 4) batchnorm (training stats) in-place on d_out
    const int nelem = BB * CC * HWSZ;
    dim3 gs(CC, BB);
    bn_stats_kernel<<<gs, 256>>>(out);
    bn_finalize_kernel<<<1, CC>>>(gamma, beta);
    bn_apply_kernel<<<nelem / 256, 256>>>(out);
}

// round 8
// speedup vs baseline: 4.0325x; 1.0468x over previous
#include <cuda_runtime.h>
#include <cuda_bf16.h>
#include <cstdint>

// Problem constants
#define BB 8
#define CC 128
#define HH 128
#define WW 128
#define HWSZ (HH*WW)          // 16384

// Scratch (device globals: allocation-free)
__device__ float g_off  [(size_t)BB * 2 * CC * HWSZ];   // conv1 out (B,2C,H,W)
__device__ float g_xT   [(size_t)BB * HWSZ * CC];       // x    transposed (B,H,W,C), tf32
__device__ float g_xoffT[(size_t)BB * HWSZ * CC];       // deformed, transposed (B,H,W,C), tf32
__device__ float g_wp1  [(size_t)9 * 256 * 128];        // w_off  packed (t,oc,ic), tf32
__device__ float g_wp2  [(size_t)9 * 128 * 128];        // w_conv packed (t,oc,ic), tf32
__device__ float g_part[CC][BB][2];
__device__ float g_scale[CC];
__device__ float g_shift[CC];

__device__ __forceinline__ float tf32r(float v) {
    float r;
    asm("cvt.rna.tf32.f32 %0, %1;" : "=f"(r) : "f"(v));
    return r;
}
__device__ __forceinline__ uint32_t smem_u32(const void* p) {
    uint32_t a;
    asm("{ .reg .u64 t; cvta.to.shared.u64 t, %1; cvt.u32.u64 %0, t; }"
        : "=r"(a) : "l"(p));
    return a;
}
#define CP_ASYNC16(dst, src, sz) \
    asm volatile("cp.async.cg.shared.global [%0], [%1], 16, %2;" \
                 :: "r"(dst), "l"(src), "r"(sz))
#define CP_COMMIT()  asm volatile("cp.async.commit_group;")
#define CP_WAIT1()   asm volatile("cp.async.wait_group 1;")
#define CP_WAIT0()   asm volatile("cp.async.wait_group 0;")
#define LDSM_X4(r0, r1, r2, r3, addr) \
    asm volatile("ldmatrix.sync.aligned.m8n8.x4.shared.b16 {%0,%1,%2,%3}, [%4];" \
                 : "=r"(r0), "=r"(r1), "=r"(r2), "=r"(r3) : "r"(addr))

// ---------------------------------------------------------------------------
// Implicit-GEMM conv 3x3 via warp-level tf32 mma.sync.
// CTA: D[128 oc x 128 px] (ONE image row), 256 threads / 8 warps as
// 2 (m) x 4 (n), warp tile 64 oc x 32 px (128 regs -> 2 CTAs per SM).
// K = 1152 = 36 chunks of (1 tap x 32 ic); constant (dy,dx) per chunk,
// 4 k8-steps per chunk. 3-stage cp.async pipeline; per-CTA barriers give
// cross-CTA latency slack on each SM.
// SMEM row stride LDA=36 floats (row-start banks 4r mod 32 -> conflict-free).
// ---------------------------------------------------------------------------
#define NTHR   256
#define LDA    36
#define ATILE  (128 * LDA * 4)              // 18432 B
#define STAGE  (2 * ATILE)                  // 36864 B  (A then B)
#define NSTAGE 3
#define SMEM_TOTAL_CONV (NSTAGE * STAGE)    // 110592 B
#define LDT    132                          // epilogue transpose stride (floats)

__global__ void __launch_bounds__(NTHR, 2)
conv_mma_kernel(const float* __restrict__ xT,   // (B,H,W,C) tf32
                const float* __restrict__ wp,   // (9,OC,128) tf32
                const float* __restrict__ bias, // (OC,) or nullptr
                float* __restrict__ out,        // (B,OC,H,W)
                int OC, int do_relu)
{
    extern __shared__ char smem[];
    const uint32_t sbase = smem_u32(smem);

    const int tid  = threadIdx.x;
    const int wid  = tid >> 5;
    const int lane = tid & 31;
    const int wm   = wid & 1;                 // warp m (2): 64 oc each
    const int wn   = wid >> 1;                // warp n (4): 32 px each

    const int row = blockIdx.x;               // 0 .. BB*HH-1
    const int b   = row >> 7;
    const int y   = row & 127;
    const int ocb = blockIdx.y << 7;

    // ldmatrix per-lane addressing (byte offsets within a tile)
    const int l8   = lane & 7;
    const int tsel = lane >> 3;               // matrix index 0..3
    uint32_t aoff[4];
    #pragma unroll
    for (int mt = 0; mt < 4; mt++)
        aoff[mt] = (uint32_t)(((wm * 64 + mt * 16 + (tsel & 1) * 8 + l8) * LDA
                               + (tsel >> 1) * 4) * 4);
    uint32_t boff[2];
    #pragma unroll
    for (int p = 0; p < 2; p++)
        boff[p] = (uint32_t)(((wn * 32 + (2 * p + (tsel >> 1)) * 8 + l8) * LDA
                              + (tsel & 1) * 4) * 4);

    float acc[4][4][4];
    #pragma unroll
    for (int mt = 0; mt < 4; mt++)
        #pragma unroll
        for (int nt = 0; nt < 4; nt++)
            #pragma unroll
            for (int i = 0; i < 4; i++) acc[mt][nt][i] = 0.f;

    // ---- async fill of one chunk (tap t, 32-ic block) into stage st
    auto issue_chunk = [&](int kb, int st) {
        const int t   = kb >> 2;
        const int ic0 = (kb & 3) << 5;
        const int dy  = t / 3 - 1;
        const int dx  = t % 3 - 1;
        const uint32_t dA = sbase + (uint32_t)(st * STAGE);
        const uint32_t dB = dA + ATILE;
        // A: 128 oc x 32 ic = 1024 float4 (4 per thread)
        #pragma unroll
        for (int i = 0; i < 4; i++) {
            const int v = tid + i * NTHR;
            const int r = v >> 3;             // oc 0..127
            const int g = v & 7;              // ic float4 group
            const float* src = wp + ((size_t)(t * OC + ocb + r)) * 128 + ic0 + g * 4;
            CP_ASYNC16(dA + (uint32_t)(r * (LDA * 4) + g * 16), src, 16);
        }
        // B: 128 px x 32 ic = 1024 float4 (4 per thread)
        const int gy = y + dy;
        const bool oky = ((unsigned)gy < 128u);
        #pragma unroll
        for (int i = 0; i < 4; i++) {
            const int v = tid + i * NTHR;
            const int r = v >> 3;             // pixel 0..127
            const int g = v & 7;
            const int gx = r + dx;
            const bool ok = oky && ((unsigned)gx < 128u);
            const float* src = xT + (((size_t)b * 128 + (ok ? gy : 0)) * 128
                                     + (ok ? gx : 0)) * 128 + ic0 + g * 4;
            CP_ASYNC16(dB + (uint32_t)(r * (LDA * 4) + g * 16), src, ok ? 16 : 0);
        }
        CP_COMMIT();
    };

    issue_chunk(0, 0);
    issue_chunk(1, 1);

    int st = 0;
    for (int kb = 0; kb < 36; kb++) {
        if (kb < 35) { CP_WAIT1(); } else { CP_WAIT0(); }
        __syncthreads();                     // fills of kb visible; all warps
                                             // past compute kb-1 -> stage free
        if (kb + 2 < 36) {
            int st2 = st + 2; if (st2 >= NSTAGE) st2 -= NSTAGE;
            issue_chunk(kb + 2, st2);
        }

        const uint32_t sA = sbase + (uint32_t)(st * STAGE);
        const uint32_t sB = sA + ATILE;

        #pragma unroll
        for (int s = 0; s < 4; s++) {
            const uint32_t kbyte = (uint32_t)(s * 32);
            uint32_t af[4][4], bf[4][2];
            #pragma unroll
            for (int mt = 0; mt < 4; mt++)
                LDSM_X4(af[mt][0], af[mt][1], af[mt][2], af[mt][3],
                        sA + aoff[mt] + kbyte);
            #pragma unroll
            for (int p = 0; p < 2; p++)
                LDSM_X4(bf[2*p][0], bf[2*p][1], bf[2*p+1][0], bf[2*p+1][1],
                        sB + boff[p] + kbyte);
            #pragma unroll
            for (int mt = 0; mt < 4; mt++)
                #pragma unroll
                for (int nt = 0; nt < 4; nt++)
                    asm volatile(
                        "mma.sync.aligned.m16n8k8.row.col.f32.tf32.tf32.f32 "
                        "{%0,%1,%2,%3}, {%4,%5,%6,%7}, {%8,%9}, {%0,%1,%2,%3};"
                        : "+f"(acc[mt][nt][0]), "+f"(acc[mt][nt][1]),
                          "+f"(acc[mt][nt][2]), "+f"(acc[mt][nt][3])
                        : "r"(af[mt][0]), "r"(af[mt][1]), "r"(af[mt][2]), "r"(af[mt][3]),
                          "r"(bf[nt][0]), "r"(bf[nt][1]));
        }
        if (++st >= NSTAGE) st = 0;
    }

    // ---- epilogue: bias + relu into SMEM transpose buffer, coalesced store
    __syncthreads();
    const int lr = lane >> 2;
    const int lc = lane & 3;
    float* s_t = (float*)smem;                // [oc][px], stride LDT
    #pragma unroll
    for (int mt = 0; mt < 4; mt++) {
        const int r0 = wm * 64 + mt * 16 + lr;
        const float bv0 = bias ? bias[ocb + r0]     : 0.f;
        const float bv1 = bias ? bias[ocb + r0 + 8] : 0.f;
        #pragma unroll
        for (int nt = 0; nt < 4; nt++) {
            const int c0 = wn * 32 + nt * 8 + 2 * lc;
            float v0 = acc[mt][nt][0] + bv0;
            float v1 = acc[mt][nt][1] + bv0;
            float v2 = acc[mt][nt][2] + bv1;
            float v3 = acc[mt][nt][3] + bv1;
            if (do_relu) {
                v0 = fmaxf(v0, 0.f); v1 = fmaxf(v1, 0.f);
                v2 = fmaxf(v2, 0.f); v3 = fmaxf(v3, 0.f);
            }
            *(float2*)(s_t + r0 * LDT + c0)       = make_float2(v0, v1);
            *(float2*)(s_t + (r0 + 8) * LDT + c0) = make_float2(v2, v3);
        }
    }
    __syncthreads();

    for (int idx = tid; idx < 128 * 32; idx += NTHR) {
        const int oc = idx >> 5;
        const int xg = idx & 31;
        float4 v = *(float4*)(s_t + oc * LDT + xg * 4);
        *(float4*)(out + ((size_t)b * OC + ocb + oc) * HWSZ + y * WW + xg * 4) = v;
    }
}

// ---------------------------------------------------------------------------
// Transpose (B,C,HW) -> (B,HW,C) with tf32 rounding.
// ---------------------------------------------------------------------------
__global__ void transpose_tf32_kernel(const float* __restrict__ in,
                                      float* __restrict__ outT)
{
    __shared__ float tile[32][33];
    const int b  = blockIdx.z;
    const int c0 = blockIdx.y << 5;
    const int q0 = blockIdx.x << 5;
    const int tx = threadIdx.x;          // 32
    const int ty = threadIdx.y;          // 8
    #pragma unroll
    for (int i = ty; i < 32; i += 8)
        tile[i][tx] = in[((size_t)b * CC + c0 + i) * HWSZ + q0 + tx];
    __syncthreads();
    #pragma unroll
    for (int j = ty; j < 32; j += 8)
        outT[((size_t)b * HWSZ + q0 + j) * CC + c0 + tx] = tf32r(tile[tx][j]);
}

// Pack weights (OC,128,3,3) -> (9,OC,128), tf32-rounded.
__global__ void pack_w_kernel(const float* __restrict__ w,
                              float* __restrict__ wpk, int OC)
{
    const int idx = blockIdx.x * 256 + threadIdx.x;
    if (idx >= OC * 128 * 9) return;
    const int oc = idx / (128 * 9);
    const int r  = idx - oc * (128 * 9);
    const int ic = r / 9;
    const int t  = r - ic * 9;
    wpk[((size_t)t * OC + oc) * 128 + ic] = tf32r(w[idx]);
}

// ---------------------------------------------------------------------------
// Fused deformable bilinear sampling + transpose: writes (B,H,W,C) tf32
// directly (quirky-reshape offset semantics preserved, sampling in fp32).
// ---------------------------------------------------------------------------
__global__ void deformT_kernel(const float* __restrict__ x,
                               const float* __restrict__ off,
                               float* __restrict__ xoT)
{
    __shared__ float tile[32][33];
    const int b  = blockIdx.z;
    const int c0 = blockIdx.y << 5;
    const int q0 = blockIdx.x << 5;
    const int tx = threadIdx.x;
    const int ty = threadIdx.y;

    #pragma unroll
    for (int i = ty; i < 32; i += 8) {
        const int c = c0 + i;
        const int q = q0 + tx;
        const int p = b * CC + c;
        const int pi = q >> 7;
        const int pj = q & 127;

        const float2 o2 = *(const float2*)(off + (size_t)p * 2 * HWSZ + 2 * q);
        float yc = fminf(fmaxf(o2.x + (float)pi, 0.f), 127.f);
        float xc = fminf(fmaxf(o2.y + (float)pj, 0.f), 127.f);
        float y0f = floorf(yc), y1f = ceilf(yc);
        float x0f = floorf(xc), x1f = ceilf(xc);
        int y0 = (int)y0f, y1 = (int)y1f;
        int x0 = (int)x0f, x1 = (int)x1f;

        const float* img = x + (size_t)p * HWSZ;
        float v_lt = img[y0 * WW + x0];
        float v_rb = img[y1 * WW + x1];
        float v_lb = img[y0 * WW + x1];
        float v_rt = img[y1 * WW + x0];

        float dy = yc - y0f;
        float dx = xc - x0f;
        float v_t = v_lt + (v_rt - v_lt) * dy;
        float v_b = v_lb + (v_rb - v_lb) * dy;
        tile[i][tx] = tf32r(v_t + (v_b - v_t) * dx);
    }
    __syncthreads();
    #pragma unroll
    for (int j = ty; j < 32; j += 8)
        xoT[((size_t)b * HWSZ + q0 + j) * CC + c0 + tx] = tile[tx][j];
}

// ---------------------------------------------------------------------------
// BatchNorm (training stats), deterministic 2-stage.
// ---------------------------------------------------------------------------
__global__ void bn_stats_kernel(const float* __restrict__ ych)
{
    const int c = blockIdx.x;
    const int b = blockIdx.y;
    const float* p = ych + ((size_t)b * CC + c) * HWSZ;
    float s = 0.f, s2 = 0.f;
    for (int q = threadIdx.x; q < HWSZ; q += 256) {
        float v = p[q];
        s += v; s2 += v * v;
    }
    __shared__ float rs[256], rs2[256];
    rs[threadIdx.x] = s; rs2[threadIdx.x] = s2;
    __syncthreads();
    for (int st = 128; st > 0; st >>= 1) {
        if (threadIdx.x < st) {
            rs[threadIdx.x]  += rs[threadIdx.x + st];
            rs2[threadIdx.x] += rs2[threadIdx.x + st];
        }
        __syncthreads();
    }
    if (threadIdx.x == 0) { g_part[c][b][0] = rs[0]; g_part[c][b][1] = rs2[0]; }
}

__global__ void bn_finalize_kernel(const float* __restrict__ gamma,
                                   const float* __restrict__ beta)
{
    const int c = threadIdx.x;
    float s = 0.f, s2 = 0.f;
    #pragma unroll
    for (int b = 0; b < BB; b++) { s += g_part[c][b][0]; s2 += g_part[c][b][1]; }
    const float n = (float)(BB * HWSZ);
    float mean = s / n;
    float var  = s2 / n - mean * mean;
    float sc   = gamma[c] * rsqrtf(var + 1e-5f);
    g_scale[c] = sc;
    g_shift[c] = beta[c] - mean * sc;
}

__global__ void bn_apply_kernel(float* __restrict__ ych)
{
    const int gid = blockIdx.x * 256 + threadIdx.x;
    const int c = (gid >> 14) & 127;
    ych[gid] = fmaf(ych[gid], g_scale[c], g_shift[c]);
}

// ---------------------------------------------------------------------------
extern "C" void kernel_launch(void* const* d_in, const int* in_sizes, int n_in,
                              void* d_out, int out_size)
{
    const float* x      = (const float*)d_in[0];
    const float* w_off  = (const float*)d_in[1];
    const float* w_conv = (const float*)d_in[2];
    const float* b_conv = (const float*)d_in[3];
    const float* gamma  = (const float*)d_in[4];
    const float* beta   = (const float*)d_in[5];
    float* out = (float*)d_out;

    float *off, *xT, *xoffT, *wp1, *wp2;
    cudaGetSymbolAddress((void**)&off,   g_off);
    cudaGetSymbolAddress((void**)&xT,    g_xT);
    cudaGetSymbolAddress((void**)&xoffT, g_xoffT);
    cudaGetSymbolAddress((void**)&wp1,   g_wp1);
    cudaGetSymbolAddress((void**)&wp2,   g_wp2);

    cudaFuncSetAttribute(conv_mma_kernel,
                         cudaFuncAttributeMaxDynamicSharedMemorySize, SMEM_TOTAL_CONV);

    // 0) transpose x -> xT (tf32), pack both weight tensors
    dim3 tg(HWSZ / 32, CC / 32, BB), tb(32, 8);
    transpose_tf32_kernel<<<tg, tb>>>(x, xT);
    pack_w_kernel<<<(256 * 128 * 9 + 255) / 256, 256>>>(w_off, wp1, 256);
    pack_w_kernel<<<(128 * 128 * 9 + 255) / 256, 256>>>(w_conv, wp2, 128);

    // 1) offsets = conv3x3(x, w_off), OC=256
    dim3 g1(BB * HH, 2);
    conv_mma_kernel<<<g1, NTHR, SMEM_TOTAL_CONV>>>(xT, wp1, nullptr, off, 256, 0);

    // 2) fused deformable sampling + transpose -> xoffT (tf32)
    deformT_kernel<<<tg, tb>>>(x, off, xoffT);

    // 3) y = relu(conv3x3(x_off, w_conv) + b_conv), OC=128 -> d_out
    dim3 g2(BB * HH, 1);
    conv_mma_kernel<<<g2, NTHR, SMEM_TOTAL_CONV>>>(xoffT, wp2, b_conv, out, 128, 1);

    // 4) batchnorm (training stats) in-place on d_out
    const int nelem = BB * CC * HWSZ;
    dim3 gs(CC, BB);
    bn_stats_kernel<<<gs, 256>>>(out);
    bn_finalize_kernel<<<1, CC>>>(gamma, beta);
    bn_apply_kernel<<<nelem / 256, 256>>>(out);
}